// round 14
// baseline (speedup 1.0000x reference)
#include <cuda_runtime.h>
#include <cuda_bf16.h>
#include <cuda_fp16.h>
#include <math.h>
#include <stdint.h>

#define BATCH 4
#define SEQ   1024
#define DIMN  1024
#define HEADS 16
#define HD    64
#define ROWS  (BATCH*SEQ)   // 4096

#if defined(__CUDA_ARCH__) && defined(__CUDA_ARCH_FEAT_SM103_ALL)
#define HAS_TC 1
#else
#define HAS_TC 0
#endif

// -------- scratch (device globals: no allocation allowed) --------
__device__ float g_x1  [ROWS * DIMN];               // fp32 residual after attn
__device__ __nv_bfloat16 g_a  [ROWS * DIMN];        // LN1/attn out (bf16) or LN2 out (fp16, reinterpret)
__device__ __half        g_h  [ROWS * 4 * DIMN];    // gelu output fp16 (mlp2 A operand)
__device__ __nv_bfloat16 g_qk [ROWS * 2 * DIMN];    // q,k rows (width 2048), bf16
__device__ __nv_bfloat16 g_vt [BATCH * HEADS * HD * SEQ];  // v transposed [b][h][d][seq]
// transposed weights
#define WOFF_QKV  0
#define WOFF_PROJ (3072 * 1024)
#define WBF_TOTAL (WOFF_PROJ + 1024 * 1024)
__device__ __nv_bfloat16 g_wt_bf[WBF_TOTAL];        // qkv + proj, bf16 Wt[n][k]
__device__ __half g_w1_16[4096 * 1024];             // mlp_w1^T fp16 [n=4096][k=1024]
__device__ __half g_w2_16[1024 * 4096];             // mlp_w2^T fp16 [n=1024][k=4096]

// idesc: dtype F32 (1<<4), atype/btype F16=0 BF16=1, N field = (N/8)<<17, M=128 (8<<24)
#define IDESC_BF16_128 ((1u<<4) | (1u<<7) | (1u<<10) | (16u<<17) | (8u<<24))
#define IDESC_FP16_128 ((1u<<4) | (16u<<17) | (8u<<24))
#define IDESC_BF16_256 ((1u<<4) | (1u<<7) | (1u<<10) | (32u<<17) | (8u<<24))
#define IDESC_FP16_256 ((1u<<4) | (32u<<17) | (8u<<24))

// ================= PTX helpers (guarded) =================
__device__ __forceinline__ uint32_t smem_u32(const void* p) {
    uint32_t a;
    asm("{ .reg .u64 t; cvta.to.shared.u64 t, %1; cvt.u32.u64 %0, t; }" : "=r"(a) : "l"(p));
    return a;
}
#if HAS_TC
__device__ __forceinline__ uint32_t elect_one() {
    uint32_t pred;
    asm volatile("{\n\t.reg .pred p;\n\telect.sync _|p, 0xFFFFFFFF;\n\tselp.b32 %0, 1, 0, p;\n\t}" : "=r"(pred));
    return pred;
}
__device__ __forceinline__ uint64_t make_sw128_desc(uint32_t addr) {
    const uint64_t BASE = (2ull << 61) | (1ull << 46) | (64ull << 32) | (1ull << 16);
    return BASE | ((uint64_t)(addr >> 4) & 0x3FFF);
}
__device__ __forceinline__ void tc_mma_f16_ss(uint32_t d, uint64_t ad, uint64_t bd,
                                              uint32_t idesc, uint32_t acc) {
    asm volatile(
        "{\n\t.reg .pred p;\n\tsetp.ne.u32 p, %4, 0;\n\t"
        "tcgen05.mma.cta_group::1.kind::f16 [%0], %1, %2, %3, {%5, %5, %5, %5}, p;\n\t}"
        :: "r"(d), "l"(ad), "l"(bd), "r"(idesc), "r"(acc), "r"(0u) : "memory");
}
__device__ __forceinline__ void tc_mma_f16_ts(uint32_t d, uint32_t a, uint64_t bd,
                                              uint32_t idesc, uint32_t acc) {
    asm volatile(
        "{\n\t.reg .pred p;\n\tsetp.ne.u32 p, %4, 0;\n\t"
        "tcgen05.mma.cta_group::1.kind::f16 [%0], [%1], %2, %3, {%5, %5, %5, %5}, p;\n\t}"
        :: "r"(d), "r"(a), "l"(bd), "r"(idesc), "r"(acc), "r"(0u) : "memory");
}
#define TC_ALLOC(sm, n)   asm volatile("tcgen05.alloc.cta_group::1.sync.aligned.shared::cta.b32 [%0], %1;" :: "r"(sm), "r"(n) : "memory")
#define TC_DEALLOC(t, n)  asm volatile("tcgen05.dealloc.cta_group::1.sync.aligned.b32 %0, %1;" :: "r"(t), "r"(n))
#define TC_RELINQ()       asm volatile("tcgen05.relinquish_alloc_permit.cta_group::1.sync.aligned;")
#define TC_COMMIT(mb)     asm volatile("tcgen05.commit.cta_group::1.mbarrier::arrive::one.shared::cluster.b64 [%0];" :: "r"(mb) : "memory")
#define TC_FENCE_AFTER()  asm volatile("tcgen05.fence::after_thread_sync;" ::: "memory")
#define TC_FENCE_BEFORE() asm volatile("tcgen05.fence::before_thread_sync;" ::: "memory")
#define TC_WAIT_LD()      asm volatile("tcgen05.wait::ld.sync.aligned;" ::: "memory")
#define TC_WAIT_ST()      asm volatile("tcgen05.wait::st.sync.aligned;" ::: "memory")
#define FENCE_ASYNC()     asm volatile("fence.proxy.async.shared::cta;" ::: "memory")
#define MBAR_INIT(mb, c)  asm volatile("mbarrier.init.shared.b64 [%0], %1;" :: "r"(mb), "r"(c) : "memory")
#define MBAR_ARRIVE(mb)   asm volatile("mbarrier.arrive.shared.b64 _, [%0];" :: "r"(mb) : "memory")
#define CP_ASYNC16(d, s)  asm volatile("cp.async.cg.shared.global [%0], [%1], 16;" :: "r"(d), "l"(s) : "memory")
#define CP_COMMIT()       asm volatile("cp.async.commit_group;" ::: "memory")
#define CP_WAIT(n)        asm volatile("cp.async.wait_group %0;" :: "n"(n) : "memory")

__device__ __forceinline__ void mbar_wait(uint32_t mb, uint32_t parity) {
    uint32_t done;
    asm volatile(
        "{\n\t.reg .pred p;\n\t"
        "mbarrier.try_wait.parity.acquire.cta.shared::cta.b64 p, [%1], %2;\n\t"
        "selp.b32 %0, 1, 0, p;\n\t}"
        : "=r"(done) : "r"(mb), "r"(parity) : "memory");
    if (!done) {
        asm volatile(
            "{\n\t.reg .pred P1;\n\t"
            "WL_%=:\n\t"
            "mbarrier.try_wait.parity.acquire.cta.shared::cta.b64 P1, [%0], %1, 0x989680;\n\t"
            "@P1 bra.uni WD_%=;\n\t"
            "bra.uni WL_%=;\n\t"
            "WD_%=:\n\t}"
            :: "r"(mb), "r"(parity) : "memory");
    }
}
#define LDTM_X32(r, a) \
    asm volatile("tcgen05.ld.sync.aligned.32x32b.x32.b32 " \
        "{%0, %1, %2, %3, %4, %5, %6, %7, %8, %9, %10, %11, %12, %13, %14, %15, " \
        "%16, %17, %18, %19, %20, %21, %22, %23, %24, %25, %26, %27, %28, %29, %30, %31}, [%32];" \
        : "=r"((r)[0]), "=r"((r)[1]), "=r"((r)[2]), "=r"((r)[3]), "=r"((r)[4]), "=r"((r)[5]), \
          "=r"((r)[6]), "=r"((r)[7]), "=r"((r)[8]), "=r"((r)[9]), "=r"((r)[10]), "=r"((r)[11]), \
          "=r"((r)[12]), "=r"((r)[13]), "=r"((r)[14]), "=r"((r)[15]), "=r"((r)[16]), "=r"((r)[17]), \
          "=r"((r)[18]), "=r"((r)[19]), "=r"((r)[20]), "=r"((r)[21]), "=r"((r)[22]), "=r"((r)[23]), \
          "=r"((r)[24]), "=r"((r)[25]), "=r"((r)[26]), "=r"((r)[27]), "=r"((r)[28]), "=r"((r)[29]), \
          "=r"((r)[30]), "=r"((r)[31]) : "r"(a))
#define STTM_X16(a, r) \
    asm volatile("tcgen05.st.sync.aligned.32x32b.x16.b32 [%0], " \
        "{%1, %2, %3, %4, %5, %6, %7, %8, %9, %10, %11, %12, %13, %14, %15, %16};" \
        :: "r"(a), \
           "r"((r)[0]), "r"((r)[1]), "r"((r)[2]), "r"((r)[3]), \
           "r"((r)[4]), "r"((r)[5]), "r"((r)[6]), "r"((r)[7]), \
           "r"((r)[8]), "r"((r)[9]), "r"((r)[10]), "r"((r)[11]), \
           "r"((r)[12]), "r"((r)[13]), "r"((r)[14]), "r"((r)[15]) : "memory")
#endif  // HAS_TC

__device__ __forceinline__ uint32_t pack2(float x, float y) {      // bf16x2
    __nv_bfloat162 h = __floats2bfloat162_rn(x, y);
    return *reinterpret_cast<uint32_t*>(&h);
}
__device__ __forceinline__ uint32_t pack2h(float x, float y) {     // fp16x2
    __half2 h = __floats2half2_rn(x, y);
    return *reinterpret_cast<uint32_t*>(&h);
}
__device__ __forceinline__ uint32_t swz(uint32_t off) { return off ^ ((off >> 3) & 0x70); }
__device__ __forceinline__ float bf2f(__nv_bfloat16 v) { return __bfloat162float(v); }

// ---------------- weight transpose pre-pass: W[K][N] fp32 -> Wt[n][k] ----------------
template<int OUT>
__global__ void __launch_bounds__(256) wsplit_kernel(
    const float* __restrict__ W, void* __restrict__ th, int K, int N)
{
    __shared__ float t[32][33];
    int n0 = blockIdx.x * 32, k0 = blockIdx.y * 32;
    int tid = threadIdx.x;
    int tx = tid & 31, ty = tid >> 5;
    #pragma unroll
    for (int j = 0; j < 4; j++)
        t[ty + 8 * j][tx] = W[(size_t)(k0 + ty + 8 * j) * N + n0 + tx];
    __syncthreads();
    int p = tid & 15;
    #pragma unroll
    for (int half = 0; half < 2; half++) {
        int nl = (tid >> 4) + half * 16;
        float v0 = t[2 * p][nl];
        float v1 = t[2 * p + 1][nl];
        size_t o = (size_t)(n0 + nl) * K + k0 + 2 * p;
        if (OUT) *(uint32_t*)((__half*)th + o) = pack2h(v0, v1);
        else     *(uint32_t*)((__nv_bfloat16*)th + o) = pack2(v0, v1);
    }
}

// ========== GEMM, 256xNT CTA tile, single pass (dtype via idesc) ==========
// NT=128: 2 CTAs/SM, TMEM 256. NT=256: 1 CTA/SM, TMEM 512.
// MODE 1: Ch(fp16) = gelu(AB+bias) ; MODE 2: C(fp32) = resid + gate*(AB+bias)
// MODE 3: qkv: cols<2048 -> Ch (bf16, width 2048); cols>=2048 -> Vth (bf16) transposed
// SMEM/stage: A rb0@0, rb1@16K; B@32K (NT*128 bytes)
#define OFF_TILES 1024

template<int MODE, int NT>
__global__ void __launch_bounds__(256, 2)
tc_gemm_kernel(const __nv_bfloat16* __restrict__ A, const __nv_bfloat16* __restrict__ B,
               uint32_t idesc, const float* __restrict__ bias, float* __restrict__ C,
               void* __restrict__ Ch, __nv_bfloat16* __restrict__ Vth,
               int M, int N, int K,
               const float* __restrict__ resid, const float* __restrict__ gate)
{
    const int BUFSZ = 32768 + NT * 128;   // 48K or 64K
    const int NREG  = 2 + NT / 128;       // 3 or 4 16KB regions
#if HAS_TC
    extern __shared__ __align__(1024) char smem[];
    uint32_t smem_base = smem_u32(smem);
    int tid = threadIdx.x;
    int wid = tid >> 5;
    int brow = blockIdx.y * 256;
    int bcol = blockIdx.x * NT;

    if (wid == 0) TC_ALLOC(smem_base, 2 * NT);
    if (tid == 0) { MBAR_INIT(smem_base + 16, 1); MBAR_INIT(smem_base + 24, 1); }
    __syncthreads();
    uint32_t tmem;
    asm volatile("ld.shared.b32 %0, [%1];" : "=r"(tmem) : "r"(smem_base));
    if (wid == 0) TC_RELINQ();

    const int NC = K >> 6;

    auto load_chunk = [&](int c, int b) {
        uint32_t bufb = smem_base + OFF_TILES + (uint32_t)b * BUFSZ;
        int k0 = c << 6;
        #pragma unroll
        for (int i = 0; i < NREG; i++) {
            #pragma unroll
            for (int u = 0; u < 4; u++) {
                int idx = u * 256 + tid;
                int r = idx >> 3;
                int o = (idx & 7) * 16;
                uint32_t so = (uint32_t)(i * 16384) + swz((uint32_t)(r * 128 + o));
                const __nv_bfloat16* src;
                if (i == 0)      src = A + (size_t)(brow + r) * K + k0;
                else if (i == 1) src = A + (size_t)(brow + 128 + r) * K + k0;
                else if (i == 2) src = B + (size_t)(bcol + r) * K + k0;
                else             src = B + (size_t)(bcol + 128 + r) * K + k0;
                CP_ASYNC16(bufb + so, (const char*)src + o);
            }
        }
        CP_COMMIT();
    };

    load_chunk(0, 0);

    uint32_t ph0 = 0, ph1 = 0;
    for (int c = 0; c < NC; c++) {
        int b = c & 1;
        if (c + 1 < NC) {
            int nb = (c + 1) & 1;
            if (c >= 1) {
                if (nb == 0) { mbar_wait(smem_base + 16, ph0); ph0 ^= 1; }
                else         { mbar_wait(smem_base + 24, ph1); ph1 ^= 1; }
            }
            load_chunk(c + 1, nb);
            CP_WAIT(1);
        } else {
            CP_WAIT(0);
        }
        FENCE_ASYNC();
        __syncthreads();
        if (wid == 0) {
            if (elect_one()) {
                uint32_t tb = smem_base + OFF_TILES + (uint32_t)b * BUFSZ;
                uint64_t dB = make_sw128_desc(tb + 32768);
                #pragma unroll
                for (int rb = 0; rb < 2; rb++) {
                    uint32_t d = tmem + (uint32_t)rb * NT;
                    uint64_t dA = make_sw128_desc(tb + rb * 16384);
                    #pragma unroll
                    for (int ks = 0; ks < 4; ks++)
                        tc_mma_f16_ss(d, dA + ks * 2, dB + ks * 2, idesc,
                                      (c == 0 && ks == 0) ? 0u : 1u);
                }
                TC_COMMIT(smem_base + 16 + 8 * b);
            }
        }
    }
    {
        int lb = (NC - 1) & 1;
        if (lb == 0) mbar_wait(smem_base + 16, ph0);
        else         mbar_wait(smem_base + 24, ph1);
    }
    TC_FENCE_AFTER();

    // ---- epilogue: warps 0-3 -> rowblock 0, warps 4-7 -> rowblock 1
    {
        int lane = tid & 31;
        int sp = (tid >> 5) & 3;
        int half = tid >> 7;
        int row = brow + half * 128 + sp * 32 + lane;
        float gv = (MODE == 2) ? gate[0] : 0.f;
        #pragma unroll
        for (int cb = 0; cb < NT / 32; cb++) {
            uint32_t regs[32];
            LDTM_X32(regs, tmem + half * NT + cb * 32);
            TC_WAIT_LD();
            int cbase = bcol + cb * 32;
            #pragma unroll
            for (int j = 0; j < 8; j++) {
                float4 bb = *(const float4*)(bias + cbase + j * 4);
                float v0 = __uint_as_float(regs[j * 4 + 0]) + bb.x;
                float v1 = __uint_as_float(regs[j * 4 + 1]) + bb.y;
                float v2 = __uint_as_float(regs[j * 4 + 2]) + bb.z;
                float v3 = __uint_as_float(regs[j * 4 + 3]) + bb.w;
                if (MODE == 1) {
                    size_t ro = (size_t)row * N + cbase + j * 4;
                    v0 = 0.5f * v0 * (1.0f + erff(v0 * 0.7071067811865475f));
                    v1 = 0.5f * v1 * (1.0f + erff(v1 * 0.7071067811865475f));
                    v2 = 0.5f * v2 * (1.0f + erff(v2 * 0.7071067811865475f));
                    v3 = 0.5f * v3 * (1.0f + erff(v3 * 0.7071067811865475f));
                    uint2 hh;
                    hh.x = pack2h(v0, v1);
                    hh.y = pack2h(v2, v3);
                    *(uint2*)((__half*)Ch + ro) = hh;
                } else if (MODE == 2) {
                    size_t ro = (size_t)row * N + cbase + j * 4;
                    float4 rr = *(const float4*)(resid + ro);
                    *(float4*)(C + ro) =
                        make_float4(rr.x + gv * v0, rr.y + gv * v1,
                                    rr.z + gv * v2, rr.w + gv * v3);
                } else { // MODE 3 (qkv, bf16)
                    float vv[4] = {v0, v1, v2, v3};
                    if (cbase < 2048) {
                        size_t ro = (size_t)row * 2048 + cbase + j * 4;
                        uint2 hh;
                        hh.x = pack2(v0, v1);
                        hh.y = pack2(v2, v3);
                        *(uint2*)((__nv_bfloat16*)Ch + ro) = hh;
                    } else {
                        int bidx = row >> 10, seq = row & 1023;
                        #pragma unroll
                        for (int e = 0; e < 4; e++) {
                            int col2 = cbase + j * 4 + e - 2048;
                            int hloc = col2 >> 6, d = col2 & 63;
                            size_t vo = ((size_t)((bidx * HEADS + hloc) * HD + d)) * SEQ + seq;
                            Vth[vo] = __float2bfloat16(vv[e]);
                        }
                    }
                }
            }
        }
        TC_FENCE_BEFORE();
    }
    __syncthreads();
    if (wid == 0) TC_DEALLOC(tmem, 2 * NT);

#else  // ---------------- SIMT fallback (compiles only; never runs on sm_103a) ----------------
    int tid = threadIdx.x;
    int brow = blockIdx.y * 256;
    int bcol = blockIdx.x * NT;
    int ty = tid >> 4, tx = tid & 15;
    float gv = (MODE == 2 && gate) ? gate[0] : 0.f;
    for (int i = 0; i < 16; i++) {
        for (int j = 0; j < NT / 16; j++) {
            int r = brow + ty * 16 + i;
            int c = bcol + tx * (NT / 16) + j;
            float acc = 0.f;
            for (int k = 0; k < K; k++)
                acc = fmaf(bf2f(A[(size_t)r * K + k]), bf2f(B[(size_t)c * K + k]), acc);
            acc += bias[c];
            if (MODE == 1) {
                acc = 0.5f * acc * (1.0f + erff(acc * 0.7071067811865475f));
                ((__half*)Ch)[(size_t)r * N + c] = __float2half(acc);
            } else if (MODE == 2) {
                size_t off = (size_t)r * N + c;
                C[off] = resid[off] + gv * acc;
            } else {
                if (c < 2048) {
                    ((__nv_bfloat16*)Ch)[(size_t)r * 2048 + c] = __float2bfloat16(acc);
                } else {
                    int col2 = c - 2048;
                    int bidx = r >> 10, seq = r & 1023;
                    size_t vo = ((size_t)((bidx * HEADS + (col2 >> 6)) * HD + (col2 & 63))) * SEQ + seq;
                    Vth[vo] = __float2bfloat16(acc);
                }
            }
        }
    }
#endif
}

// ---------------- LayerNorm: fp32 in -> bf16 (OUT=0) or fp16 (OUT=1) ----------------
template<int OUT>
__global__ void __launch_bounds__(256) ln_kernel(
    const float* __restrict__ x, const float* __restrict__ g,
    const float* __restrict__ b, void* __restrict__ y)
{
    int row = blockIdx.x;
    int tid = threadIdx.x;
    const float* xr = x + (size_t)row * DIMN;
    float4 v = *(const float4*)(xr + tid * 4);
    float s  = v.x + v.y + v.z + v.w;
    float s2 = v.x*v.x + v.y*v.y + v.z*v.z + v.w*v.w;
    #pragma unroll
    for (int o = 16; o > 0; o >>= 1) {
        s  += __shfl_xor_sync(0xffffffffu, s,  o);
        s2 += __shfl_xor_sync(0xffffffffu, s2, o);
    }
    __shared__ float rs[8], rs2[8];
    int w = tid >> 5, lane = tid & 31;
    if (lane == 0) { rs[w] = s; rs2[w] = s2; }
    __syncthreads();
    if (tid == 0) {
        float a = 0.f, a2 = 0.f;
        #pragma unroll
        for (int i = 0; i < 8; i++) { a += rs[i]; a2 += rs2[i]; }
        rs[0] = a; rs2[0] = a2;
    }
    __syncthreads();
    float mu   = rs[0] * (1.0f / DIMN);
    float var  = rs2[0] * (1.0f / DIMN) - mu * mu;
    float rstd = rsqrtf(var + 1e-5f);
    float4 gv = *(const float4*)(g + tid * 4);
    float4 bv = *(const float4*)(b + tid * 4);
    float o0 = (v.x - mu) * rstd * gv.x + bv.x;
    float o1 = (v.y - mu) * rstd * gv.y + bv.y;
    float o2 = (v.z - mu) * rstd * gv.z + bv.z;
    float o3 = (v.w - mu) * rstd * gv.w + bv.w;
    uint2 hh;
    if (OUT) { hh.x = pack2h(o0, o1); hh.y = pack2h(o2, o3); }
    else     { hh.x = pack2(o0, o1);  hh.y = pack2(o2, o3);  }
    *(uint2*)((char*)y + ((size_t)row * DIMN + tid * 4) * 2) = hh;
}

// ======== tcgen05 flash attention (bf16, fixed-max, TMEM O, 256-col TMEM, 2 CTAs/SM) ========
#define ASM_FULL0  8
#define ASM_FULL1  16
#define ASM_EK0    24
#define ASM_EK1    32
#define ASM_EV0    40
#define ASM_EV1    48
#define ASM_SDONE  56
#define ASM_PDONE  64
#define ASM_BIAS   128     // 2 x 256 floats
#define ASM_MK     2176    // 2 x 128 floats
#define ASM_MQ     3200    // 128 floats
#define ASM_QHI    4096    // 16KB
#define ASM_BUF    20480   // 2 x 32768
#define ASM_TOTAL  (20480 + 2*32768)
#define IDESC_S  ((1u<<4) | (1u<<7) | (1u<<10) | (16u<<17) | (8u<<24))
#define IDESC_PV ((1u<<4) | (1u<<7) | (1u<<10) | (8u<<17)  | (8u<<24))

__global__ void __launch_bounds__(256, 2)
attn_tc_kernel(const __nv_bfloat16* __restrict__ Qkh,
               const __nv_bfloat16* __restrict__ Vth,
               const int* __restrict__ mask, const float* __restrict__ relb,
               __nv_bfloat16* __restrict__ oh)
{
    int qt = blockIdx.x, h = blockIdx.y, bb = blockIdx.z;
    int tid = threadIdx.x;
#if HAS_TC
    extern __shared__ __align__(1024) char smem[];
    uint32_t base = smem_u32(smem);
    int wid = tid >> 5, lane = tid & 31;
    const size_t qrow0 = (size_t)(bb * SEQ + qt * 128);

    if (wid == 0) TC_ALLOC(base, 256);
    if (tid == 0) {
        MBAR_INIT(base + ASM_FULL0, 128);
        MBAR_INIT(base + ASM_FULL1, 128);
        MBAR_INIT(base + ASM_EK0, 1);
        MBAR_INIT(base + ASM_EK1, 1);
        MBAR_INIT(base + ASM_EV0, 1);
        MBAR_INIT(base + ASM_EV1, 1);
        MBAR_INIT(base + ASM_SDONE, 1);
        MBAR_INIT(base + ASM_PDONE, 1);
    }
    __syncthreads();
    uint32_t tmem;
    asm volatile("ld.shared.b32 %0, [%1];" : "=r"(tmem) : "r"(base));
    if (wid == 0) TC_RELINQ();

    float* bias_s = (float*)(smem + ASM_BIAS);
    float* mk_s   = (float*)(smem + ASM_MK);
    float* mq_s   = (float*)(smem + ASM_MQ);

    if (wid >= 4) {
        // ---------------- producers ----------------
        int pt = tid - 128;
        for (int t = 0; t < 8; t++) {
            int bsel = t & 1;
            int k0 = t * 128;
            char* buf = smem + ASM_BUF + bsel * 32768;
            if (t >= 2) mbar_wait(base + ASM_EK0 + 8 * bsel, ((t >> 1) - 1) & 1);
            #pragma unroll
            for (int i = 0; i < 8; i++) {
                int idx = i * 128 + pt;
                int r = idx >> 3, ch = idx & 7;
                size_t go = (size_t)(bb * SEQ + k0 + r) * 2048 + 1024 + h * HD + ch * 8;
                uint32_t so = swz(r * 128 + ch * 16);
                *(uint4*)(buf + so) = *(const uint4*)(Qkh + go);
            }
            if (t >= 2) mbar_wait(base + ASM_EV0 + 8 * bsel, ((t >> 1) - 1) & 1);
            #pragma unroll
            for (int i = 0; i < 8; i++) {
                int idx = i * 128 + pt;
                int d = idx >> 4, hh2 = (idx >> 3) & 1, ch = idx & 7;
                size_t go = ((size_t)((bb * HEADS + h) * HD + d)) * SEQ + k0 + hh2 * 64 + ch * 8;
                uint32_t so = (uint32_t)(hh2 * 8192) + swz(d * 128 + ch * 16);
                *(uint4*)(buf + 16384 + so) = *(const uint4*)(Vth + go);
            }
            bias_s[bsel * 256 + pt] = relb[(qt * 128 - k0 + pt + 896) * HEADS + h];
            if (pt + 128 < 255)
                bias_s[bsel * 256 + pt + 128] = relb[(qt * 128 - k0 + pt + 128 + 896) * HEADS + h];
            mk_s[bsel * 128 + pt] = (float)mask[bb * SEQ + k0 + pt];
            FENCE_ASYNC();
            MBAR_ARRIVE(base + ASM_FULL0 + 8 * bsel);
        }
    } else {
        // ---------------- consumers ----------------
        int t4 = tid;
        #pragma unroll
        for (int i = 0; i < 8; i++) {
            int idx = i * 128 + t4;
            int r = idx >> 3, ch = idx & 7;
            size_t go = (qrow0 + r) * 2048 + h * HD + ch * 8;
            uint32_t so = swz(r * 128 + ch * 16);
            *(uint4*)(smem + ASM_QHI + so) = *(const uint4*)(Qkh + go);
        }
        mq_s[t4] = (float)mask[qrow0 + t4];
        FENCE_ASYNC();
        asm volatile("bar.sync 7, 128;" ::: "memory");

        int r = wid * 32 + lane;
        float mqr = mq_s[r];
        float lrow = 0.f;
        uint32_t warpoff = (uint32_t)wid << 21;
        uint64_t dQh = make_sw128_desc(base + ASM_QHI);

        if (wid == 0 && elect_one()) {
            mbar_wait(base + ASM_FULL0, 0);
            uint64_t dKh = make_sw128_desc(base + ASM_BUF);
            #pragma unroll
            for (int ks = 0; ks < 4; ks++)
                tc_mma_f16_ss(tmem, dQh + ks * 2, dKh + ks * 2, IDESC_S, ks > 0 ? 1u : 0u);
            TC_COMMIT(base + ASM_SDONE);
        }

        for (int t = 0; t < 8; t++) {
            int bsel = t & 1;
            uint32_t bufb = base + ASM_BUF + bsel * 32768;
            const float* bsf = bias_s + bsel * 256;
            const float* mkf = mk_s + bsel * 128;
            mbar_wait(base + ASM_FULL0 + 8 * bsel, (t >> 1) & 1);
            mbar_wait(base + ASM_SDONE, t & 1);
            TC_FENCE_AFTER();
            if (wid == 0 && elect_one()) MBAR_ARRIVE(base + ASM_EK0 + 8 * bsel);
            if (t >= 1) {
                mbar_wait(base + ASM_PDONE, (t - 1) & 1);
                TC_FENCE_AFTER();
                if (wid == 0 && elect_one()) MBAR_ARRIVE(base + ASM_EV0 + 8 * ((t - 1) & 1));
            }

            float rsum = 0.f;
            #pragma unroll
            for (int j = 0; j < 4; j++) {
                uint32_t sr[32];
                LDTM_X32(sr, tmem + j * 32);
                TC_WAIT_LD();
                uint32_t ph[16];
                #pragma unroll
                for (int k = 0; k < 16; k++) {
                    int c = j * 32 + 2 * k;
                    float va = __uint_as_float(sr[2 * k])     * 0.125f + bsf[r - c + 127];
                    float vb = __uint_as_float(sr[2 * k + 1]) * 0.125f + bsf[r - (c + 1) + 127];
                    va = (mqr * mkf[c]     >= 0.5f) ? va : -1e9f;
                    vb = (mqr * mkf[c + 1] >= 0.5f) ? vb : -1e9f;
                    float ea = __expf(va);
                    float eb = __expf(vb);
                    rsum += ea + eb;
                    ph[k] = pack2(ea, eb);
                }
                STTM_X16(tmem + 192 + j * 16 + warpoff, ph);
            }
            TC_WAIT_ST();
            lrow += rsum;
            TC_FENCE_BEFORE();
            asm volatile("bar.sync 7, 128;" ::: "memory");

            if (wid == 0 && elect_one()) {
                if (t < 7) {
                    int nb = (t + 1) & 1;
                    mbar_wait(base + ASM_FULL0 + 8 * nb, ((t + 1) >> 1) & 1);
                    uint64_t dKh = make_sw128_desc(base + ASM_BUF + nb * 32768);
                    #pragma unroll
                    for (int ks = 0; ks < 4; ks++)
                        tc_mma_f16_ss(tmem, dQh + ks * 2, dKh + ks * 2, IDESC_S, ks > 0 ? 1u : 0u);
                    TC_COMMIT(base + ASM_SDONE);
                }
                uint64_t dVh0 = make_sw128_desc(bufb + 16384);
                uint64_t dVh1 = make_sw128_desc(bufb + 16384 + 8192);
                #pragma unroll
                for (int ks = 0; ks < 8; ks++) {
                    uint64_t dvh = (ks < 4 ? dVh0 : dVh1) + (ks & 3) * 2;
                    tc_mma_f16_ts(tmem + 128, tmem + 192 + ks * 8, dvh, IDESC_PV,
                                  (t == 0 && ks == 0) ? 0u : 1u);
                }
                TC_COMMIT(base + ASM_PDONE);
            }
        }

        mbar_wait(base + ASM_PDONE, 1);
        TC_FENCE_AFTER();
        uint32_t pv0[32], pv1[32];
        LDTM_X32(pv0, tmem + 128);
        TC_WAIT_LD();
        LDTM_X32(pv1, tmem + 160);
        TC_WAIT_LD();
        TC_FENCE_BEFORE();
        float inv = 1.0f / lrow;
        size_t orow = (qrow0 + r) * DIMN + h * HD;
        uint32_t* po = (uint32_t*)(oh + orow);
        #pragma unroll
        for (int j = 0; j < 16; j++)
            po[j] = pack2(__uint_as_float(pv0[2 * j]) * inv, __uint_as_float(pv0[2 * j + 1]) * inv);
        #pragma unroll
        for (int j = 0; j < 16; j++)
            po[16 + j] = pack2(__uint_as_float(pv1[2 * j]) * inv, __uint_as_float(pv1[2 * j + 1]) * inv);
    }
    __syncthreads();
    if (wid == 0) TC_DEALLOC(tmem, 256);
#else
    // naive fallback (compiles only)
    int r = tid;
    if (r < 128) {
        int q = qt * 128 + r;
        size_t qro = (size_t)(bb * SEQ + q) * 2048 + h * HD;
        float mqr = (float)mask[bb * SEQ + q];
        float lrow = 0.f, O[64];
        for (int d = 0; d < 64; d++) O[d] = 0.f;
        for (int k = 0; k < SEQ; k++) {
            float s = 0.f;
            size_t kro = (size_t)(bb * SEQ + k) * 2048 + 1024 + h * HD;
            for (int d = 0; d < 64; d++)
                s = fmaf(bf2f(Qkh[qro + d]), bf2f(Qkh[kro + d]), s);
            s = s * 0.125f + relb[(q - k + SEQ - 1) * HEADS + h];
            float mk2 = (float)mask[bb * SEQ + k];
            s = (mqr * mk2 >= 0.5f) ? s : -1e9f;
            float p = expf(s);
            lrow += p;
            size_t vro = ((size_t)((bb * HEADS + h) * HD)) * SEQ + k;
            for (int d = 0; d < 64; d++)
                O[d] += p * bf2f(Vth[vro + (size_t)d * SEQ]);
        }
        size_t orow = (size_t)(bb * SEQ + q) * DIMN + h * HD;
        for (int d = 0; d < 64; d++)
            oh[orow + d] = __float2bfloat16(O[d] / lrow);
    }
#endif
}

// ---------------- host launcher ----------------
extern "C" void kernel_launch(void* const* d_in, const int* in_sizes, int n_in,
                              void* d_out, int out_size)
{
    const float* x      = (const float*)d_in[0];
    const int*   mask   = (const int*)  d_in[1];
    const float* ln1_g  = (const float*)d_in[2];
    const float* ln1_b  = (const float*)d_in[3];
    const float* qkv_w  = (const float*)d_in[4];
    const float* qkv_b  = (const float*)d_in[5];
    const float* proj_w = (const float*)d_in[6];
    const float* proj_b = (const float*)d_in[7];
    const float* relb   = (const float*)d_in[8];
    const float* ln2_g  = (const float*)d_in[9];
    const float* ln2_b  = (const float*)d_in[10];
    const float* mlp_w1 = (const float*)d_in[11];
    const float* mlp_b1 = (const float*)d_in[12];
    const float* mlp_w2 = (const float*)d_in[13];
    const float* mlp_b2 = (const float*)d_in[14];
    const float* gate1  = (const float*)d_in[15];
    const float* gate2  = (const float*)d_in[16];
    float* out = (float*)d_out;

    float *x1b;
    __nv_bfloat16 *ab, *wtb, *qkh, *vth;
    __half *hb, *w1h, *w2h;
    cudaGetSymbolAddress((void**)&x1b, g_x1);
    cudaGetSymbolAddress((void**)&ab,  g_a);
    cudaGetSymbolAddress((void**)&hb,  g_h);
    cudaGetSymbolAddress((void**)&wtb, g_wt_bf);
    cudaGetSymbolAddress((void**)&qkh, g_qk);
    cudaGetSymbolAddress((void**)&vth, g_vt);
    cudaGetSymbolAddress((void**)&w1h, g_w1_16);
    cudaGetSymbolAddress((void**)&w2h, g_w2_16);

    int smem_g128 = OFF_TILES + 2 * (32768 + 128 * 128);   //  99328
    int smem_g256 = OFF_TILES + 2 * (32768 + 256 * 128);   // 132096
    cudaFuncSetAttribute(tc_gemm_kernel<1,256>, cudaFuncAttributeMaxDynamicSharedMemorySize, smem_g256);
    cudaFuncSetAttribute(tc_gemm_kernel<2,128>, cudaFuncAttributeMaxDynamicSharedMemorySize, smem_g128);
    cudaFuncSetAttribute(tc_gemm_kernel<3,256>, cudaFuncAttributeMaxDynamicSharedMemorySize, smem_g256);
    cudaFuncSetAttribute(attn_tc_kernel, cudaFuncAttributeMaxDynamicSharedMemorySize, ASM_TOTAL);

    // 0) weight transpose pre-pass
    wsplit_kernel<0><<<dim3(3072/32, 1024/32), 256>>>(qkv_w,  wtb + WOFF_QKV,  1024, 3072);
    wsplit_kernel<0><<<dim3(1024/32, 1024/32), 256>>>(proj_w, wtb + WOFF_PROJ, 1024, 1024);
    wsplit_kernel<1><<<dim3(4096/32, 1024/32), 256>>>(mlp_w1, w1h, 1024, 4096);
    wsplit_kernel<1><<<dim3(1024/32, 4096/32), 256>>>(mlp_w2, w2h, 4096, 1024);

    // 1) LN1 -> a (bf16)
    ln_kernel<0><<<ROWS, 256>>>(x, ln1_g, ln1_b, ab);
    // 2) QKV GEMM (bf16, 256x256 tiles) -> qk + vt
    tc_gemm_kernel<3,256><<<dim3(3 * DIMN / 256, ROWS / 256), 256, smem_g256>>>(
        ab, wtb + WOFF_QKV, IDESC_BF16_256, qkv_b, nullptr, qkh, vth,
        ROWS, 3 * DIMN, DIMN, nullptr, nullptr);
    // 3) tcgen05 attention (bf16) -> a
    attn_tc_kernel<<<dim3(SEQ / 128, HEADS, BATCH), 256, ASM_TOTAL>>>(
        qkh, vth, mask, relb, ab);
    // 4) x1 = x + gate1 * (a @ proj_w + proj_b)  (bf16, 256x128)
    tc_gemm_kernel<2,128><<<dim3(DIMN / 128, ROWS / 256), 256, smem_g128>>>(
        ab, wtb + WOFF_PROJ, IDESC_BF16_128, proj_b, x1b, nullptr, nullptr,
        ROWS, DIMN, DIMN, x, gate1);
    // 5) LN2 -> a (fp16, reinterpret buffer)
    ln_kernel<1><<<ROWS, 256>>>(x1b, ln2_g, ln2_b, ab);
    // 6) h = gelu(a @ mlp_w1 + mlp_b1)  (fp16, 256x256 tiles)
    tc_gemm_kernel<1,256><<<dim3(4 * DIMN / 256, ROWS / 256), 256, smem_g256>>>(
        (const __nv_bfloat16*)ab, (const __nv_bfloat16*)w1h, IDESC_FP16_256, mlp_b1,
        nullptr, hb, nullptr, ROWS, 4 * DIMN, DIMN, nullptr, nullptr);
    // 7) out = x1 + gate2 * (h @ mlp_w2 + mlp_b2)  (fp16, 256x128)
    tc_gemm_kernel<2,128><<<dim3(DIMN / 128, ROWS / 256), 256, smem_g128>>>(
        (const __nv_bfloat16*)hb, (const __nv_bfloat16*)w2h, IDESC_FP16_128, mlp_b2,
        out, nullptr, nullptr, ROWS, DIMN, 4 * DIMN, x1b, gate2);
}

// round 15
// speedup vs baseline: 1.1373x; 1.1373x over previous
#include <cuda_runtime.h>
#include <cuda_bf16.h>
#include <cuda_fp16.h>
#include <math.h>
#include <stdint.h>

#define BATCH 4
#define SEQ   1024
#define DIMN  1024
#define HEADS 16
#define HD    64
#define ROWS  (BATCH*SEQ)   // 4096

#if defined(__CUDA_ARCH__) && defined(__CUDA_ARCH_FEAT_SM103_ALL)
#define HAS_TC 1
#else
#define HAS_TC 0
#endif

// -------- scratch (device globals: no allocation allowed) --------
__device__ float g_x1  [ROWS * DIMN];               // fp32 residual after attn
__device__ __nv_bfloat16 g_a  [ROWS * DIMN];        // LN1/attn out (bf16) or LN2 out (fp16, reinterpret)
__device__ __half        g_h  [ROWS * 4 * DIMN];    // gelu output fp16 (mlp2 A operand)
__device__ __nv_bfloat16 g_qk [ROWS * 2 * DIMN];    // q,k rows (width 2048), bf16
__device__ __nv_bfloat16 g_vt [BATCH * HEADS * HD * SEQ];  // v transposed [b][h][d][seq]
// transposed weights
#define WOFF_QKV  0
#define WOFF_PROJ (3072 * 1024)
#define WBF_TOTAL (WOFF_PROJ + 1024 * 1024)
__device__ __nv_bfloat16 g_wt_bf[WBF_TOTAL];        // qkv + proj, bf16 Wt[n][k]
__device__ __half g_w1_16[4096 * 1024];             // mlp_w1^T fp16 [n=4096][k=1024]
__device__ __half g_w2_16[1024 * 4096];             // mlp_w2^T fp16 [n=1024][k=4096]

// idesc: dtype F32 (1<<4), atype/btype F16=0 BF16=1, N=128 (16<<17), M=128 (8<<24)
#define IDESC_BF16 ((1u<<4) | (1u<<7) | (1u<<10) | (16u<<17) | (8u<<24))
#define IDESC_FP16 ((1u<<4) | (16u<<17) | (8u<<24))

// ================= PTX helpers (guarded) =================
__device__ __forceinline__ uint32_t smem_u32(const void* p) {
    uint32_t a;
    asm("{ .reg .u64 t; cvta.to.shared.u64 t, %1; cvt.u32.u64 %0, t; }" : "=r"(a) : "l"(p));
    return a;
}
#if HAS_TC
__device__ __forceinline__ uint32_t elect_one() {
    uint32_t pred;
    asm volatile("{\n\t.reg .pred p;\n\telect.sync _|p, 0xFFFFFFFF;\n\tselp.b32 %0, 1, 0, p;\n\t}" : "=r"(pred));
    return pred;
}
__device__ __forceinline__ uint64_t make_sw128_desc(uint32_t addr) {
    const uint64_t BASE = (2ull << 61) | (1ull << 46) | (64ull << 32) | (1ull << 16);
    return BASE | ((uint64_t)(addr >> 4) & 0x3FFF);
}
__device__ __forceinline__ void tc_mma_f16_ss(uint32_t d, uint64_t ad, uint64_t bd,
                                              uint32_t idesc, uint32_t acc) {
    asm volatile(
        "{\n\t.reg .pred p;\n\tsetp.ne.u32 p, %4, 0;\n\t"
        "tcgen05.mma.cta_group::1.kind::f16 [%0], %1, %2, %3, {%5, %5, %5, %5}, p;\n\t}"
        :: "r"(d), "l"(ad), "l"(bd), "r"(idesc), "r"(acc), "r"(0u) : "memory");
}
__device__ __forceinline__ void tc_mma_f16_ts(uint32_t d, uint32_t a, uint64_t bd,
                                              uint32_t idesc, uint32_t acc) {
    asm volatile(
        "{\n\t.reg .pred p;\n\tsetp.ne.u32 p, %4, 0;\n\t"
        "tcgen05.mma.cta_group::1.kind::f16 [%0], [%1], %2, %3, {%5, %5, %5, %5}, p;\n\t}"
        :: "r"(d), "r"(a), "l"(bd), "r"(idesc), "r"(acc), "r"(0u) : "memory");
}
#define TC_ALLOC(sm, n)   asm volatile("tcgen05.alloc.cta_group::1.sync.aligned.shared::cta.b32 [%0], %1;" :: "r"(sm), "r"(n) : "memory")
#define TC_DEALLOC(t, n)  asm volatile("tcgen05.dealloc.cta_group::1.sync.aligned.b32 %0, %1;" :: "r"(t), "r"(n))
#define TC_RELINQ()       asm volatile("tcgen05.relinquish_alloc_permit.cta_group::1.sync.aligned;")
#define TC_COMMIT(mb)     asm volatile("tcgen05.commit.cta_group::1.mbarrier::arrive::one.shared::cluster.b64 [%0];" :: "r"(mb) : "memory")
#define TC_FENCE_AFTER()  asm volatile("tcgen05.fence::after_thread_sync;" ::: "memory")
#define TC_FENCE_BEFORE() asm volatile("tcgen05.fence::before_thread_sync;" ::: "memory")
#define TC_WAIT_LD()      asm volatile("tcgen05.wait::ld.sync.aligned;" ::: "memory")
#define TC_WAIT_ST()      asm volatile("tcgen05.wait::st.sync.aligned;" ::: "memory")
#define FENCE_ASYNC()     asm volatile("fence.proxy.async.shared::cta;" ::: "memory")
#define MBAR_INIT(mb, c)  asm volatile("mbarrier.init.shared.b64 [%0], %1;" :: "r"(mb), "r"(c) : "memory")
#define MBAR_ARRIVE(mb)   asm volatile("mbarrier.arrive.shared.b64 _, [%0];" :: "r"(mb) : "memory")
#define CP_ASYNC16(d, s)  asm volatile("cp.async.cg.shared.global [%0], [%1], 16;" :: "r"(d), "l"(s) : "memory")
#define CP_COMMIT()       asm volatile("cp.async.commit_group;" ::: "memory")
#define CP_WAIT(n)        asm volatile("cp.async.wait_group %0;" :: "n"(n) : "memory")

__device__ __forceinline__ void mbar_wait(uint32_t mb, uint32_t parity) {
    uint32_t done;
    asm volatile(
        "{\n\t.reg .pred p;\n\t"
        "mbarrier.try_wait.parity.acquire.cta.shared::cta.b64 p, [%1], %2;\n\t"
        "selp.b32 %0, 1, 0, p;\n\t}"
        : "=r"(done) : "r"(mb), "r"(parity) : "memory");
    if (!done) {
        asm volatile(
            "{\n\t.reg .pred P1;\n\t"
            "WL_%=:\n\t"
            "mbarrier.try_wait.parity.acquire.cta.shared::cta.b64 P1, [%0], %1, 0x989680;\n\t"
            "@P1 bra.uni WD_%=;\n\t"
            "bra.uni WL_%=;\n\t"
            "WD_%=:\n\t}"
            :: "r"(mb), "r"(parity) : "memory");
    }
}
#define LDTM_X32(r, a) \
    asm volatile("tcgen05.ld.sync.aligned.32x32b.x32.b32 " \
        "{%0, %1, %2, %3, %4, %5, %6, %7, %8, %9, %10, %11, %12, %13, %14, %15, " \
        "%16, %17, %18, %19, %20, %21, %22, %23, %24, %25, %26, %27, %28, %29, %30, %31}, [%32];" \
        : "=r"((r)[0]), "=r"((r)[1]), "=r"((r)[2]), "=r"((r)[3]), "=r"((r)[4]), "=r"((r)[5]), \
          "=r"((r)[6]), "=r"((r)[7]), "=r"((r)[8]), "=r"((r)[9]), "=r"((r)[10]), "=r"((r)[11]), \
          "=r"((r)[12]), "=r"((r)[13]), "=r"((r)[14]), "=r"((r)[15]), "=r"((r)[16]), "=r"((r)[17]), \
          "=r"((r)[18]), "=r"((r)[19]), "=r"((r)[20]), "=r"((r)[21]), "=r"((r)[22]), "=r"((r)[23]), \
          "=r"((r)[24]), "=r"((r)[25]), "=r"((r)[26]), "=r"((r)[27]), "=r"((r)[28]), "=r"((r)[29]), \
          "=r"((r)[30]), "=r"((r)[31]) : "r"(a))
#define STTM_X16(a, r) \
    asm volatile("tcgen05.st.sync.aligned.32x32b.x16.b32 [%0], " \
        "{%1, %2, %3, %4, %5, %6, %7, %8, %9, %10, %11, %12, %13, %14, %15, %16};" \
        :: "r"(a), \
           "r"((r)[0]), "r"((r)[1]), "r"((r)[2]), "r"((r)[3]), \
           "r"((r)[4]), "r"((r)[5]), "r"((r)[6]), "r"((r)[7]), \
           "r"((r)[8]), "r"((r)[9]), "r"((r)[10]), "r"((r)[11]), \
           "r"((r)[12]), "r"((r)[13]), "r"((r)[14]), "r"((r)[15]) : "memory")
#endif  // HAS_TC

__device__ __forceinline__ uint32_t pack2(float x, float y) {      // bf16x2
    __nv_bfloat162 h = __floats2bfloat162_rn(x, y);
    return *reinterpret_cast<uint32_t*>(&h);
}
__device__ __forceinline__ uint32_t pack2h(float x, float y) {     // fp16x2
    __half2 h = __floats2half2_rn(x, y);
    return *reinterpret_cast<uint32_t*>(&h);
}
__device__ __forceinline__ uint32_t swz(uint32_t off) { return off ^ ((off >> 3) & 0x70); }
__device__ __forceinline__ float bf2f(__nv_bfloat16 v) { return __bfloat162float(v); }

// ---------------- weight transpose pre-pass: W[K][N] fp32 -> Wt[n][k] ----------------
// Tile (k:128, n:32); uint4 stores (8 halves) => 8 threads/row = full 128B store transaction.
template<int OUT>
__global__ void __launch_bounds__(256) wsplit_kernel(
    const float* __restrict__ W, void* __restrict__ th, int K, int N)
{
    __shared__ float t[128][33];
    int n0 = blockIdx.x * 32, k0 = blockIdx.y * 128;
    int tid = threadIdx.x;
    int tx = tid & 31, kb = tid >> 5;        // kb 0..7
    #pragma unroll
    for (int j = 0; j < 16; j++)
        t[kb + 8 * j][tx] = W[(size_t)(k0 + kb + 8 * j) * N + n0 + tx];
    __syncthreads();
    int nl = tid >> 3;            // output row 0..31
    int q  = tid & 7;             // 16B chunk 0..7 (chunks q and q+8)
    #pragma unroll
    for (int half = 0; half < 2; half++) {
        int c = q + half * 8;     // chunk index 0..15, covers k = c*8 .. c*8+7
        uint4 v;
        uint32_t* vp = (uint32_t*)&v;
        #pragma unroll
        for (int i = 0; i < 4; i++) {
            float a = t[c * 8 + 2 * i][nl];
            float b = t[c * 8 + 2 * i + 1][nl];
            vp[i] = OUT ? pack2h(a, b) : pack2(a, b);
        }
        size_t o = (size_t)(n0 + nl) * K + k0 + c * 8;
        if (OUT) *(uint4*)((__half*)th + o) = v;
        else     *(uint4*)((__nv_bfloat16*)th + o) = v;
    }
}

// ========== GEMM, 256x128 CTA tile, single pass (dtype via idesc), 2 CTAs/SM ==========
// MODE 1: Ch(fp16) = gelu(AB+bias) ; MODE 2: C(fp32) = resid + gate*(AB+bias)
// MODE 3: qkv: cols<2048 -> Ch (bf16, width 2048); cols>=2048 -> Vth (bf16) transposed
// SMEM buffer (48KB): A rb0@0, rb1@16K; B@32K
#define OFF_TILES 1024
#define GBUFSZ    49152

template<int MODE>
__global__ void __launch_bounds__(256, 2)
tc_gemm_kernel(const __nv_bfloat16* __restrict__ A, const __nv_bfloat16* __restrict__ B,
               uint32_t idesc, const float* __restrict__ bias, float* __restrict__ C,
               void* __restrict__ Ch, __nv_bfloat16* __restrict__ Vth,
               int M, int N, int K,
               const float* __restrict__ resid, const float* __restrict__ gate)
{
#if HAS_TC
    extern __shared__ __align__(1024) char smem[];
    uint32_t smem_base = smem_u32(smem);
    int tid = threadIdx.x;
    int wid = tid >> 5;
    int brow = blockIdx.y * 256;
    int bcol = blockIdx.x * 128;

    if (wid == 0) TC_ALLOC(smem_base, 256);
    if (tid == 0) { MBAR_INIT(smem_base + 16, 1); MBAR_INIT(smem_base + 24, 1); }
    __syncthreads();
    uint32_t tmem;
    asm volatile("ld.shared.b32 %0, [%1];" : "=r"(tmem) : "r"(smem_base));
    if (wid == 0) TC_RELINQ();

    const int NC = K >> 6;

    auto load_chunk = [&](int c, int b) {
        uint32_t bufb = smem_base + OFF_TILES + (uint32_t)b * GBUFSZ;
        int k0 = c << 6;
        #pragma unroll
        for (int i = 0; i < 3; i++) {
            #pragma unroll
            for (int u = 0; u < 4; u++) {
                int idx = u * 256 + tid;
                int r = idx >> 3;
                int o = (idx & 7) * 16;
                uint32_t so = (uint32_t)(i * 16384) + swz((uint32_t)(r * 128 + o));
                const __nv_bfloat16* src;
                if (i == 0)      src = A + (size_t)(brow + r) * K + k0;
                else if (i == 1) src = A + (size_t)(brow + 128 + r) * K + k0;
                else             src = B + (size_t)(bcol + r) * K + k0;
                CP_ASYNC16(bufb + so, (const char*)src + o);
            }
        }
        CP_COMMIT();
    };

    load_chunk(0, 0);

    uint32_t ph0 = 0, ph1 = 0;
    for (int c = 0; c < NC; c++) {
        int b = c & 1;
        if (c + 1 < NC) {
            int nb = (c + 1) & 1;
            if (c >= 1) {
                if (nb == 0) { mbar_wait(smem_base + 16, ph0); ph0 ^= 1; }
                else         { mbar_wait(smem_base + 24, ph1); ph1 ^= 1; }
            }
            load_chunk(c + 1, nb);
            CP_WAIT(1);
        } else {
            CP_WAIT(0);
        }
        FENCE_ASYNC();
        __syncthreads();
        if (wid == 0) {
            if (elect_one()) {
                uint32_t tb = smem_base + OFF_TILES + (uint32_t)b * GBUFSZ;
                uint64_t dB = make_sw128_desc(tb + 32768);
                #pragma unroll
                for (int rb = 0; rb < 2; rb++) {
                    uint32_t d = tmem + (uint32_t)rb * 128;
                    uint64_t dA = make_sw128_desc(tb + rb * 16384);
                    #pragma unroll
                    for (int ks = 0; ks < 4; ks++)
                        tc_mma_f16_ss(d, dA + ks * 2, dB + ks * 2, idesc,
                                      (c == 0 && ks == 0) ? 0u : 1u);
                }
                TC_COMMIT(smem_base + 16 + 8 * b);
            }
        }
    }
    {
        int lb = (NC - 1) & 1;
        if (lb == 0) mbar_wait(smem_base + 16, ph0);
        else         mbar_wait(smem_base + 24, ph1);
    }
    TC_FENCE_AFTER();

    // ---- epilogue: warps 0-3 -> rowblock 0, warps 4-7 -> rowblock 1
    {
        int lane = tid & 31;
        int sp = (tid >> 5) & 3;
        int half = tid >> 7;
        int row = brow + half * 128 + sp * 32 + lane;
        float gv = (MODE == 2) ? gate[0] : 0.f;
        #pragma unroll
        for (int cb = 0; cb < 4; cb++) {
            uint32_t regs[32];
            LDTM_X32(regs, tmem + half * 128 + cb * 32);
            TC_WAIT_LD();
            int cbase = bcol + cb * 32;
            #pragma unroll
            for (int j = 0; j < 8; j++) {
                float4 bb = *(const float4*)(bias + cbase + j * 4);
                float v0 = __uint_as_float(regs[j * 4 + 0]) + bb.x;
                float v1 = __uint_as_float(regs[j * 4 + 1]) + bb.y;
                float v2 = __uint_as_float(regs[j * 4 + 2]) + bb.z;
                float v3 = __uint_as_float(regs[j * 4 + 3]) + bb.w;
                if (MODE == 1) {
                    size_t ro = (size_t)row * N + cbase + j * 4;
                    v0 = 0.5f * v0 * (1.0f + erff(v0 * 0.7071067811865475f));
                    v1 = 0.5f * v1 * (1.0f + erff(v1 * 0.7071067811865475f));
                    v2 = 0.5f * v2 * (1.0f + erff(v2 * 0.7071067811865475f));
                    v3 = 0.5f * v3 * (1.0f + erff(v3 * 0.7071067811865475f));
                    uint2 hh;
                    hh.x = pack2h(v0, v1);
                    hh.y = pack2h(v2, v3);
                    *(uint2*)((__half*)Ch + ro) = hh;
                } else if (MODE == 2) {
                    size_t ro = (size_t)row * N + cbase + j * 4;
                    float4 rr = *(const float4*)(resid + ro);
                    *(float4*)(C + ro) =
                        make_float4(rr.x + gv * v0, rr.y + gv * v1,
                                    rr.z + gv * v2, rr.w + gv * v3);
                } else { // MODE 3 (qkv, bf16)
                    float vv[4] = {v0, v1, v2, v3};
                    if (cbase < 2048) {
                        size_t ro = (size_t)row * 2048 + cbase + j * 4;
                        uint2 hh;
                        hh.x = pack2(v0, v1);
                        hh.y = pack2(v2, v3);
                        *(uint2*)((__nv_bfloat16*)Ch + ro) = hh;
                    } else {
                        int bidx = row >> 10, seq = row & 1023;
                        #pragma unroll
                        for (int e = 0; e < 4; e++) {
                            int col2 = cbase + j * 4 + e - 2048;
                            int hloc = col2 >> 6, d = col2 & 63;
                            size_t vo = ((size_t)((bidx * HEADS + hloc) * HD + d)) * SEQ + seq;
                            Vth[vo] = __float2bfloat16(vv[e]);
                        }
                    }
                }
            }
        }
        TC_FENCE_BEFORE();
    }
    __syncthreads();
    if (wid == 0) TC_DEALLOC(tmem, 256);

#else  // ---------------- SIMT fallback (compiles only; never runs on sm_103a) ----------------
    int tid = threadIdx.x;
    int brow = blockIdx.y * 256;
    int bcol = blockIdx.x * 128;
    int ty = tid >> 4, tx = tid & 15;
    float gv = (MODE == 2 && gate) ? gate[0] : 0.f;
    for (int i = 0; i < 16; i++) {
        for (int j = 0; j < 8; j++) {
            int r = brow + ty * 16 + i;
            int c = bcol + tx * 8 + j;
            float acc = 0.f;
            for (int k = 0; k < K; k++)
                acc = fmaf(bf2f(A[(size_t)r * K + k]), bf2f(B[(size_t)c * K + k]), acc);
            acc += bias[c];
            if (MODE == 1) {
                acc = 0.5f * acc * (1.0f + erff(acc * 0.7071067811865475f));
                ((__half*)Ch)[(size_t)r * N + c] = __float2half(acc);
            } else if (MODE == 2) {
                size_t off = (size_t)r * N + c;
                C[off] = resid[off] + gv * acc;
            } else {
                if (c < 2048) {
                    ((__nv_bfloat16*)Ch)[(size_t)r * 2048 + c] = __float2bfloat16(acc);
                } else {
                    int col2 = c - 2048;
                    int bidx = r >> 10, seq = r & 1023;
                    size_t vo = ((size_t)((bidx * HEADS + (col2 >> 6)) * HD + (col2 & 63))) * SEQ + seq;
                    Vth[vo] = __float2bfloat16(acc);
                }
            }
        }
    }
#endif
}

// ---------------- LayerNorm: fp32 in -> bf16 (OUT=0) or fp16 (OUT=1) ----------------
template<int OUT>
__global__ void __launch_bounds__(256) ln_kernel(
    const float* __restrict__ x, const float* __restrict__ g,
    const float* __restrict__ b, void* __restrict__ y)
{
    int row = blockIdx.x;
    int tid = threadIdx.x;
    const float* xr = x + (size_t)row * DIMN;
    float4 v = *(const float4*)(xr + tid * 4);
    float s  = v.x + v.y + v.z + v.w;
    float s2 = v.x*v.x + v.y*v.y + v.z*v.z + v.w*v.w;
    #pragma unroll
    for (int o = 16; o > 0; o >>= 1) {
        s  += __shfl_xor_sync(0xffffffffu, s,  o);
        s2 += __shfl_xor_sync(0xffffffffu, s2, o);
    }
    __shared__ float rs[8], rs2[8];
    int w = tid >> 5, lane = tid & 31;
    if (lane == 0) { rs[w] = s; rs2[w] = s2; }
    __syncthreads();
    if (tid == 0) {
        float a = 0.f, a2 = 0.f;
        #pragma unroll
        for (int i = 0; i < 8; i++) { a += rs[i]; a2 += rs2[i]; }
        rs[0] = a; rs2[0] = a2;
    }
    __syncthreads();
    float mu   = rs[0] * (1.0f / DIMN);
    float var  = rs2[0] * (1.0f / DIMN) - mu * mu;
    float rstd = rsqrtf(var + 1e-5f);
    float4 gv = *(const float4*)(g + tid * 4);
    float4 bv = *(const float4*)(b + tid * 4);
    float o0 = (v.x - mu) * rstd * gv.x + bv.x;
    float o1 = (v.y - mu) * rstd * gv.y + bv.y;
    float o2 = (v.z - mu) * rstd * gv.z + bv.z;
    float o3 = (v.w - mu) * rstd * gv.w + bv.w;
    uint2 hh;
    if (OUT) { hh.x = pack2h(o0, o1); hh.y = pack2h(o2, o3); }
    else     { hh.x = pack2(o0, o1);  hh.y = pack2(o2, o3);  }
    *(uint2*)((char*)y + ((size_t)row * DIMN + tid * 4) * 2) = hh;
}

// ======== tcgen05 flash attention (bf16, fixed-max, TMEM O, 256-col TMEM, 2 CTAs/SM) ========
#define ASM_FULL0  8
#define ASM_FULL1  16
#define ASM_EK0    24
#define ASM_EK1    32
#define ASM_EV0    40
#define ASM_EV1    48
#define ASM_SDONE  56
#define ASM_PDONE  64
#define ASM_BIAS   128     // 2 x 256 floats
#define ASM_MK     2176    // 2 x 128 floats
#define ASM_MQ     3200    // 128 floats
#define ASM_QHI    4096    // 16KB
#define ASM_BUF    20480   // 2 x 32768
#define ASM_TOTAL  (20480 + 2*32768)
#define IDESC_S  ((1u<<4) | (1u<<7) | (1u<<10) | (16u<<17) | (8u<<24))
#define IDESC_PV ((1u<<4) | (1u<<7) | (1u<<10) | (8u<<17)  | (8u<<24))

__global__ void __launch_bounds__(256, 2)
attn_tc_kernel(const __nv_bfloat16* __restrict__ Qkh,
               const __nv_bfloat16* __restrict__ Vth,
               const int* __restrict__ mask, const float* __restrict__ relb,
               __nv_bfloat16* __restrict__ oh)
{
    int qt = blockIdx.x, h = blockIdx.y, bb = blockIdx.z;
    int tid = threadIdx.x;
#if HAS_TC
    extern __shared__ __align__(1024) char smem[];
    uint32_t base = smem_u32(smem);
    int wid = tid >> 5, lane = tid & 31;
    const size_t qrow0 = (size_t)(bb * SEQ + qt * 128);

    if (wid == 0) TC_ALLOC(base, 256);
    if (tid == 0) {
        MBAR_INIT(base + ASM_FULL0, 128);
        MBAR_INIT(base + ASM_FULL1, 128);
        MBAR_INIT(base + ASM_EK0, 1);
        MBAR_INIT(base + ASM_EK1, 1);
        MBAR_INIT(base + ASM_EV0, 1);
        MBAR_INIT(base + ASM_EV1, 1);
        MBAR_INIT(base + ASM_SDONE, 1);
        MBAR_INIT(base + ASM_PDONE, 1);
    }
    __syncthreads();
    uint32_t tmem;
    asm volatile("ld.shared.b32 %0, [%1];" : "=r"(tmem) : "r"(base));
    if (wid == 0) TC_RELINQ();

    float* bias_s = (float*)(smem + ASM_BIAS);
    float* mk_s   = (float*)(smem + ASM_MK);
    float* mq_s   = (float*)(smem + ASM_MQ);

    if (wid >= 4) {
        // ---------------- producers ----------------
        int pt = tid - 128;
        for (int t = 0; t < 8; t++) {
            int bsel = t & 1;
            int k0 = t * 128;
            char* buf = smem + ASM_BUF + bsel * 32768;
            if (t >= 2) mbar_wait(base + ASM_EK0 + 8 * bsel, ((t >> 1) - 1) & 1);
            #pragma unroll
            for (int i = 0; i < 8; i++) {
                int idx = i * 128 + pt;
                int r = idx >> 3, ch = idx & 7;
                size_t go = (size_t)(bb * SEQ + k0 + r) * 2048 + 1024 + h * HD + ch * 8;
                uint32_t so = swz(r * 128 + ch * 16);
                *(uint4*)(buf + so) = *(const uint4*)(Qkh + go);
            }
            if (t >= 2) mbar_wait(base + ASM_EV0 + 8 * bsel, ((t >> 1) - 1) & 1);
            #pragma unroll
            for (int i = 0; i < 8; i++) {
                int idx = i * 128 + pt;
                int d = idx >> 4, hh2 = (idx >> 3) & 1, ch = idx & 7;
                size_t go = ((size_t)((bb * HEADS + h) * HD + d)) * SEQ + k0 + hh2 * 64 + ch * 8;
                uint32_t so = (uint32_t)(hh2 * 8192) + swz(d * 128 + ch * 16);
                *(uint4*)(buf + 16384 + so) = *(const uint4*)(Vth + go);
            }
            bias_s[bsel * 256 + pt] = relb[(qt * 128 - k0 + pt + 896) * HEADS + h];
            if (pt + 128 < 255)
                bias_s[bsel * 256 + pt + 128] = relb[(qt * 128 - k0 + pt + 128 + 896) * HEADS + h];
            mk_s[bsel * 128 + pt] = (float)mask[bb * SEQ + k0 + pt];
            FENCE_ASYNC();
            MBAR_ARRIVE(base + ASM_FULL0 + 8 * bsel);
        }
    } else {
        // ---------------- consumers ----------------
        int t4 = tid;
        #pragma unroll
        for (int i = 0; i < 8; i++) {
            int idx = i * 128 + t4;
            int r = idx >> 3, ch = idx & 7;
            size_t go = (qrow0 + r) * 2048 + h * HD + ch * 8;
            uint32_t so = swz(r * 128 + ch * 16);
            *(uint4*)(smem + ASM_QHI + so) = *(const uint4*)(Qkh + go);
        }
        mq_s[t4] = (float)mask[qrow0 + t4];
        FENCE_ASYNC();
        asm volatile("bar.sync 7, 128;" ::: "memory");

        int r = wid * 32 + lane;
        float mqr = mq_s[r];
        float lrow = 0.f;
        uint32_t warpoff = (uint32_t)wid << 21;
        uint64_t dQh = make_sw128_desc(base + ASM_QHI);

        if (wid == 0 && elect_one()) {
            mbar_wait(base + ASM_FULL0, 0);
            uint64_t dKh = make_sw128_desc(base + ASM_BUF);
            #pragma unroll
            for (int ks = 0; ks < 4; ks++)
                tc_mma_f16_ss(tmem, dQh + ks * 2, dKh + ks * 2, IDESC_S, ks > 0 ? 1u : 0u);
            TC_COMMIT(base + ASM_SDONE);
        }

        for (int t = 0; t < 8; t++) {
            int bsel = t & 1;
            uint32_t bufb = base + ASM_BUF + bsel * 32768;
            const float* bsf = bias_s + bsel * 256;
            const float* mkf = mk_s + bsel * 128;
            mbar_wait(base + ASM_FULL0 + 8 * bsel, (t >> 1) & 1);
            mbar_wait(base + ASM_SDONE, t & 1);
            TC_FENCE_AFTER();
            if (wid == 0 && elect_one()) MBAR_ARRIVE(base + ASM_EK0 + 8 * bsel);
            if (t >= 1) {
                mbar_wait(base + ASM_PDONE, (t - 1) & 1);
                TC_FENCE_AFTER();
                if (wid == 0 && elect_one()) MBAR_ARRIVE(base + ASM_EV0 + 8 * ((t - 1) & 1));
            }

            float rsum = 0.f;
            #pragma unroll
            for (int j = 0; j < 4; j++) {
                uint32_t sr[32];
                LDTM_X32(sr, tmem + j * 32);
                TC_WAIT_LD();
                uint32_t ph[16];
                #pragma unroll
                for (int k = 0; k < 16; k++) {
                    int c = j * 32 + 2 * k;
                    float va = __uint_as_float(sr[2 * k])     * 0.125f + bsf[r - c + 127];
                    float vb = __uint_as_float(sr[2 * k + 1]) * 0.125f + bsf[r - (c + 1) + 127];
                    va = (mqr * mkf[c]     >= 0.5f) ? va : -1e9f;
                    vb = (mqr * mkf[c + 1] >= 0.5f) ? vb : -1e9f;
                    float ea = __expf(va);
                    float eb = __expf(vb);
                    rsum += ea + eb;
                    ph[k] = pack2(ea, eb);
                }
                STTM_X16(tmem + 192 + j * 16 + warpoff, ph);
            }
            TC_WAIT_ST();
            lrow += rsum;
            TC_FENCE_BEFORE();
            asm volatile("bar.sync 7, 128;" ::: "memory");

            if (wid == 0 && elect_one()) {
                if (t < 7) {
                    int nb = (t + 1) & 1;
                    mbar_wait(base + ASM_FULL0 + 8 * nb, ((t + 1) >> 1) & 1);
                    uint64_t dKh = make_sw128_desc(base + ASM_BUF + nb * 32768);
                    #pragma unroll
                    for (int ks = 0; ks < 4; ks++)
                        tc_mma_f16_ss(tmem, dQh + ks * 2, dKh + ks * 2, IDESC_S, ks > 0 ? 1u : 0u);
                    TC_COMMIT(base + ASM_SDONE);
                }
                uint64_t dVh0 = make_sw128_desc(bufb + 16384);
                uint64_t dVh1 = make_sw128_desc(bufb + 16384 + 8192);
                #pragma unroll
                for (int ks = 0; ks < 8; ks++) {
                    uint64_t dvh = (ks < 4 ? dVh0 : dVh1) + (ks & 3) * 2;
                    tc_mma_f16_ts(tmem + 128, tmem + 192 + ks * 8, dvh, IDESC_PV,
                                  (t == 0 && ks == 0) ? 0u : 1u);
                }
                TC_COMMIT(base + ASM_PDONE);
            }
        }

        mbar_wait(base + ASM_PDONE, 1);
        TC_FENCE_AFTER();
        uint32_t pv0[32], pv1[32];
        LDTM_X32(pv0, tmem + 128);
        TC_WAIT_LD();
        LDTM_X32(pv1, tmem + 160);
        TC_WAIT_LD();
        TC_FENCE_BEFORE();
        float inv = 1.0f / lrow;
        size_t orow = (qrow0 + r) * DIMN + h * HD;
        uint32_t* po = (uint32_t*)(oh + orow);
        #pragma unroll
        for (int j = 0; j < 16; j++)
            po[j] = pack2(__uint_as_float(pv0[2 * j]) * inv, __uint_as_float(pv0[2 * j + 1]) * inv);
        #pragma unroll
        for (int j = 0; j < 16; j++)
            po[16 + j] = pack2(__uint_as_float(pv1[2 * j]) * inv, __uint_as_float(pv1[2 * j + 1]) * inv);
    }
    __syncthreads();
    if (wid == 0) TC_DEALLOC(tmem, 256);
#else
    // naive fallback (compiles only)
    int r = tid;
    if (r < 128) {
        int q = qt * 128 + r;
        size_t qro = (size_t)(bb * SEQ + q) * 2048 + h * HD;
        float mqr = (float)mask[bb * SEQ + q];
        float lrow = 0.f, O[64];
        for (int d = 0; d < 64; d++) O[d] = 0.f;
        for (int k = 0; k < SEQ; k++) {
            float s = 0.f;
            size_t kro = (size_t)(bb * SEQ + k) * 2048 + 1024 + h * HD;
            for (int d = 0; d < 64; d++)
                s = fmaf(bf2f(Qkh[qro + d]), bf2f(Qkh[kro + d]), s);
            s = s * 0.125f + relb[(q - k + SEQ - 1) * HEADS + h];
            float mk2 = (float)mask[bb * SEQ + k];
            s = (mqr * mk2 >= 0.5f) ? s : -1e9f;
            float p = expf(s);
            lrow += p;
            size_t vro = ((size_t)((bb * HEADS + h) * HD)) * SEQ + k;
            for (int d = 0; d < 64; d++)
                O[d] += p * bf2f(Vth[vro + (size_t)d * SEQ]);
        }
        size_t orow = (size_t)(bb * SEQ + q) * DIMN + h * HD;
        for (int d = 0; d < 64; d++)
            oh[orow + d] = __float2bfloat16(O[d] / lrow);
    }
#endif
}

// ---------------- host launcher ----------------
extern "C" void kernel_launch(void* const* d_in, const int* in_sizes, int n_in,
                              void* d_out, int out_size)
{
    const float* x      = (const float*)d_in[0];
    const int*   mask   = (const int*)  d_in[1];
    const float* ln1_g  = (const float*)d_in[2];
    const float* ln1_b  = (const float*)d_in[3];
    const float* qkv_w  = (const float*)d_in[4];
    const float* qkv_b  = (const float*)d_in[5];
    const float* proj_w = (const float*)d_in[6];
    const float* proj_b = (const float*)d_in[7];
    const float* relb   = (const float*)d_in[8];
    const float* ln2_g  = (const float*)d_in[9];
    const float* ln2_b  = (const float*)d_in[10];
    const float* mlp_w1 = (const float*)d_in[11];
    const float* mlp_b1 = (const float*)d_in[12];
    const float* mlp_w2 = (const float*)d_in[13];
    const float* mlp_b2 = (const float*)d_in[14];
    const float* gate1  = (const float*)d_in[15];
    const float* gate2  = (const float*)d_in[16];
    float* out = (float*)d_out;

    float *x1b;
    __nv_bfloat16 *ab, *wtb, *qkh, *vth;
    __half *hb, *w1h, *w2h;
    cudaGetSymbolAddress((void**)&x1b, g_x1);
    cudaGetSymbolAddress((void**)&ab,  g_a);
    cudaGetSymbolAddress((void**)&hb,  g_h);
    cudaGetSymbolAddress((void**)&wtb, g_wt_bf);
    cudaGetSymbolAddress((void**)&qkh, g_qk);
    cudaGetSymbolAddress((void**)&vth, g_vt);
    cudaGetSymbolAddress((void**)&w1h, g_w1_16);
    cudaGetSymbolAddress((void**)&w2h, g_w2_16);

    int smem_gemm = OFF_TILES + 2 * GBUFSZ;   // 99328
    cudaFuncSetAttribute(tc_gemm_kernel<1>, cudaFuncAttributeMaxDynamicSharedMemorySize, smem_gemm);
    cudaFuncSetAttribute(tc_gemm_kernel<2>, cudaFuncAttributeMaxDynamicSharedMemorySize, smem_gemm);
    cudaFuncSetAttribute(tc_gemm_kernel<3>, cudaFuncAttributeMaxDynamicSharedMemorySize, smem_gemm);
    cudaFuncSetAttribute(attn_tc_kernel, cudaFuncAttributeMaxDynamicSharedMemorySize, ASM_TOTAL);

    // 0) weight transpose pre-pass (k-wide tiles, vectorized stores)
    wsplit_kernel<0><<<dim3(3072/32, 1024/128), 256>>>(qkv_w,  wtb + WOFF_QKV,  1024, 3072);
    wsplit_kernel<0><<<dim3(1024/32, 1024/128), 256>>>(proj_w, wtb + WOFF_PROJ, 1024, 1024);
    wsplit_kernel<1><<<dim3(4096/32, 1024/128), 256>>>(mlp_w1, w1h, 1024, 4096);
    wsplit_kernel<1><<<dim3(1024/32, 4096/128), 256>>>(mlp_w2, w2h, 4096, 1024);

    // 1) LN1 -> a (bf16)
    ln_kernel<0><<<ROWS, 256>>>(x, ln1_g, ln1_b, ab);
    // 2) QKV GEMM (bf16) -> qk + vt
    tc_gemm_kernel<3><<<dim3(3 * DIMN / 128, ROWS / 256), 256, smem_gemm>>>(
        ab, wtb + WOFF_QKV, IDESC_BF16, qkv_b, nullptr, qkh, vth,
        ROWS, 3 * DIMN, DIMN, nullptr, nullptr);
    // 3) tcgen05 attention (bf16) -> a
    attn_tc_kernel<<<dim3(SEQ / 128, HEADS, BATCH), 256, ASM_TOTAL>>>(
        qkh, vth, mask, relb, ab);
    // 4) x1 = x + gate1 * (a @ proj_w + proj_b)  (bf16)
    tc_gemm_kernel<2><<<dim3(DIMN / 128, ROWS / 256), 256, smem_gemm>>>(
        ab, wtb + WOFF_PROJ, IDESC_BF16, proj_b, x1b, nullptr, nullptr,
        ROWS, DIMN, DIMN, x, gate1);
    // 5) LN2 -> a (fp16, reinterpret buffer)
    ln_kernel<1><<<ROWS, 256>>>(x1b, ln2_g, ln2_b, ab);
    // 6) h = gelu(a @ mlp_w1 + mlp_b1)  (fp16 single pass)
    tc_gemm_kernel<1><<<dim3(4 * DIMN / 128, ROWS / 256), 256, smem_gemm>>>(
        (const __nv_bfloat16*)ab, (const __nv_bfloat16*)w1h, IDESC_FP16, mlp_b1,
        nullptr, hb, nullptr, ROWS, 4 * DIMN, DIMN, nullptr, nullptr);
    // 7) out = x1 + gate2 * (h @ mlp_w2 + mlp_b2)  (fp16 single pass)
    tc_gemm_kernel<2><<<dim3(DIMN / 128, ROWS / 256), 256, smem_gemm>>>(
        (const __nv_bfloat16*)hb, (const __nv_bfloat16*)w2h, IDESC_FP16, mlp_b2,
        out, nullptr, nullptr, ROWS, DIMN, 4 * DIMN, x1b, gate2);
}

// round 16
// speedup vs baseline: 1.1456x; 1.0072x over previous
#include <cuda_runtime.h>
#include <cuda_bf16.h>
#include <cuda_fp16.h>
#include <math.h>
#include <stdint.h>

#define BATCH 4
#define SEQ   1024
#define DIMN  1024
#define HEADS 16
#define HD    64
#define ROWS  (BATCH*SEQ)   // 4096

#if defined(__CUDA_ARCH__) && defined(__CUDA_ARCH_FEAT_SM103_ALL)
#define HAS_TC 1
#else
#define HAS_TC 0
#endif

// -------- scratch (device globals: no allocation allowed) --------
__device__ float g_x1  [ROWS * DIMN];               // fp32 residual after attn
__device__ __nv_bfloat16 g_a  [ROWS * DIMN];        // LN1/attn out (bf16) or LN2 out (fp16, reinterpret)
__device__ __half        g_h  [ROWS * 4 * DIMN];    // gelu output fp16 (mlp2 A operand)
__device__ __nv_bfloat16 g_qk [ROWS * 2 * DIMN];    // q,k rows (width 2048), bf16
__device__ __nv_bfloat16 g_vt [BATCH * HEADS * HD * SEQ];  // v transposed [b][h][d][seq]
// transposed weights
#define WOFF_QKV  0
#define WOFF_PROJ (3072 * 1024)
#define WBF_TOTAL (WOFF_PROJ + 1024 * 1024)
__device__ __nv_bfloat16 g_wt_bf[WBF_TOTAL];        // qkv + proj, bf16 Wt[n][k]
__device__ __half g_w1_16[4096 * 1024];             // mlp_w1^T fp16 [n=4096][k=1024]
__device__ __half g_w2_16[1024 * 4096];             // mlp_w2^T fp16 [n=1024][k=4096]

// idesc: dtype F32 (1<<4), atype/btype F16=0 BF16=1, N=128 (16<<17), M=128 (8<<24)
#define IDESC_BF16 ((1u<<4) | (1u<<7) | (1u<<10) | (16u<<17) | (8u<<24))
#define IDESC_FP16 ((1u<<4) | (16u<<17) | (8u<<24))

// ================= PTX helpers (guarded) =================
__device__ __forceinline__ uint32_t smem_u32(const void* p) {
    uint32_t a;
    asm("{ .reg .u64 t; cvta.to.shared.u64 t, %1; cvt.u32.u64 %0, t; }" : "=r"(a) : "l"(p));
    return a;
}
#define CP_ASYNC16(d, s)  asm volatile("cp.async.cg.shared.global [%0], [%1], 16;" :: "r"(d), "l"(s) : "memory")
#define CP_COMMIT()       asm volatile("cp.async.commit_group;" ::: "memory")
#define CP_WAIT(n)        asm volatile("cp.async.wait_group %0;" :: "n"(n) : "memory")
#if HAS_TC
__device__ __forceinline__ uint32_t elect_one() {
    uint32_t pred;
    asm volatile("{\n\t.reg .pred p;\n\telect.sync _|p, 0xFFFFFFFF;\n\tselp.b32 %0, 1, 0, p;\n\t}" : "=r"(pred));
    return pred;
}
__device__ __forceinline__ uint64_t make_sw128_desc(uint32_t addr) {
    const uint64_t BASE = (2ull << 61) | (1ull << 46) | (64ull << 32) | (1ull << 16);
    return BASE | ((uint64_t)(addr >> 4) & 0x3FFF);
}
__device__ __forceinline__ void tc_mma_f16_ss(uint32_t d, uint64_t ad, uint64_t bd,
                                              uint32_t idesc, uint32_t acc) {
    asm volatile(
        "{\n\t.reg .pred p;\n\tsetp.ne.u32 p, %4, 0;\n\t"
        "tcgen05.mma.cta_group::1.kind::f16 [%0], %1, %2, %3, {%5, %5, %5, %5}, p;\n\t}"
        :: "r"(d), "l"(ad), "l"(bd), "r"(idesc), "r"(acc), "r"(0u) : "memory");
}
__device__ __forceinline__ void tc_mma_f16_ts(uint32_t d, uint32_t a, uint64_t bd,
                                              uint32_t idesc, uint32_t acc) {
    asm volatile(
        "{\n\t.reg .pred p;\n\tsetp.ne.u32 p, %4, 0;\n\t"
        "tcgen05.mma.cta_group::1.kind::f16 [%0], [%1], %2, %3, {%5, %5, %5, %5}, p;\n\t}"
        :: "r"(d), "r"(a), "l"(bd), "r"(idesc), "r"(acc), "r"(0u) : "memory");
}
#define TC_ALLOC(sm, n)   asm volatile("tcgen05.alloc.cta_group::1.sync.aligned.shared::cta.b32 [%0], %1;" :: "r"(sm), "r"(n) : "memory")
#define TC_DEALLOC(t, n)  asm volatile("tcgen05.dealloc.cta_group::1.sync.aligned.b32 %0, %1;" :: "r"(t), "r"(n))
#define TC_RELINQ()       asm volatile("tcgen05.relinquish_alloc_permit.cta_group::1.sync.aligned;")
#define TC_COMMIT(mb)     asm volatile("tcgen05.commit.cta_group::1.mbarrier::arrive::one.shared::cluster.b64 [%0];" :: "r"(mb) : "memory")
#define TC_FENCE_AFTER()  asm volatile("tcgen05.fence::after_thread_sync;" ::: "memory")
#define TC_FENCE_BEFORE() asm volatile("tcgen05.fence::before_thread_sync;" ::: "memory")
#define TC_WAIT_LD()      asm volatile("tcgen05.wait::ld.sync.aligned;" ::: "memory")
#define TC_WAIT_ST()      asm volatile("tcgen05.wait::st.sync.aligned;" ::: "memory")
#define FENCE_ASYNC()     asm volatile("fence.proxy.async.shared::cta;" ::: "memory")
#define MBAR_INIT(mb, c)  asm volatile("mbarrier.init.shared.b64 [%0], %1;" :: "r"(mb), "r"(c) : "memory")
#define MBAR_ARRIVE(mb)   asm volatile("mbarrier.arrive.shared.b64 _, [%0];" :: "r"(mb) : "memory")

__device__ __forceinline__ void mbar_wait(uint32_t mb, uint32_t parity) {
    uint32_t done;
    asm volatile(
        "{\n\t.reg .pred p;\n\t"
        "mbarrier.try_wait.parity.acquire.cta.shared::cta.b64 p, [%1], %2;\n\t"
        "selp.b32 %0, 1, 0, p;\n\t}"
        : "=r"(done) : "r"(mb), "r"(parity) : "memory");
    if (!done) {
        asm volatile(
            "{\n\t.reg .pred P1;\n\t"
            "WL_%=:\n\t"
            "mbarrier.try_wait.parity.acquire.cta.shared::cta.b64 P1, [%0], %1, 0x989680;\n\t"
            "@P1 bra.uni WD_%=;\n\t"
            "bra.uni WL_%=;\n\t"
            "WD_%=:\n\t}"
            :: "r"(mb), "r"(parity) : "memory");
    }
}
#define LDTM_X32(r, a) \
    asm volatile("tcgen05.ld.sync.aligned.32x32b.x32.b32 " \
        "{%0, %1, %2, %3, %4, %5, %6, %7, %8, %9, %10, %11, %12, %13, %14, %15, " \
        "%16, %17, %18, %19, %20, %21, %22, %23, %24, %25, %26, %27, %28, %29, %30, %31}, [%32];" \
        : "=r"((r)[0]), "=r"((r)[1]), "=r"((r)[2]), "=r"((r)[3]), "=r"((r)[4]), "=r"((r)[5]), \
          "=r"((r)[6]), "=r"((r)[7]), "=r"((r)[8]), "=r"((r)[9]), "=r"((r)[10]), "=r"((r)[11]), \
          "=r"((r)[12]), "=r"((r)[13]), "=r"((r)[14]), "=r"((r)[15]), "=r"((r)[16]), "=r"((r)[17]), \
          "=r"((r)[18]), "=r"((r)[19]), "=r"((r)[20]), "=r"((r)[21]), "=r"((r)[22]), "=r"((r)[23]), \
          "=r"((r)[24]), "=r"((r)[25]), "=r"((r)[26]), "=r"((r)[27]), "=r"((r)[28]), "=r"((r)[29]), \
          "=r"((r)[30]), "=r"((r)[31]) : "r"(a))
#define STTM_X16(a, r) \
    asm volatile("tcgen05.st.sync.aligned.32x32b.x16.b32 [%0], " \
        "{%1, %2, %3, %4, %5, %6, %7, %8, %9, %10, %11, %12, %13, %14, %15, %16};" \
        :: "r"(a), \
           "r"((r)[0]), "r"((r)[1]), "r"((r)[2]), "r"((r)[3]), \
           "r"((r)[4]), "r"((r)[5]), "r"((r)[6]), "r"((r)[7]), \
           "r"((r)[8]), "r"((r)[9]), "r"((r)[10]), "r"((r)[11]), \
           "r"((r)[12]), "r"((r)[13]), "r"((r)[14]), "r"((r)[15]) : "memory")
#endif  // HAS_TC

__device__ __forceinline__ uint32_t pack2(float x, float y) {      // bf16x2
    __nv_bfloat162 h = __floats2bfloat162_rn(x, y);
    return *reinterpret_cast<uint32_t*>(&h);
}
__device__ __forceinline__ uint32_t pack2h(float x, float y) {     // fp16x2
    __half2 h = __floats2half2_rn(x, y);
    return *reinterpret_cast<uint32_t*>(&h);
}
__device__ __forceinline__ uint32_t swz(uint32_t off) { return off ^ ((off >> 3) & 0x70); }
__device__ __forceinline__ float bf2f(__nv_bfloat16 v) { return __bfloat162float(v); }

// ========= fused weight transpose+convert: all 4 matrices, one launch =========
// Each block: one 128x128 fp32 tile -> transposed 2-byte tile.
// smem tile: row k = 512B (32 chunks of 16B), chunk swizzle cs = nq ^ (k&31).
__global__ void __launch_bounds__(256) wconv_kernel(
    const float* __restrict__ qkvw, const float* __restrict__ projw,
    const float* __restrict__ w1,   const float* __restrict__ w2,
    __nv_bfloat16* __restrict__ owqkv, __nv_bfloat16* __restrict__ owproj,
    __half* __restrict__ ow1, __half* __restrict__ ow2)
{
    extern __shared__ __align__(16) char smem[];
    int b = blockIdx.x;
    const float* W; void* out; int K, N, tx, ty, f16;
    if (b < 192)      { W = qkvw;  out = owqkv;  K = 1024; N = 3072; tx = b % 24;  ty = b / 24;  f16 = 0; }
    else if (b < 256) { int r = b - 192; W = projw; out = owproj; K = 1024; N = 1024; tx = r % 8;  ty = r / 8;  f16 = 0; }
    else if (b < 512) { int r = b - 256; W = w1;    out = ow1;    K = 1024; N = 4096; tx = r % 32; ty = r / 32; f16 = 1; }
    else              { int r = b - 512; W = w2;    out = ow2;    K = 4096; N = 1024; tx = r % 8;  ty = r / 8;  f16 = 1; }
    int n0 = tx * 128, k0 = ty * 128;
    int tid = threadIdx.x;
    uint32_t sb = smem_u32(smem);

    // producer: 16 cp.async of 16B per thread (4096 chunks total)
    #pragma unroll
    for (int u = 0; u < 16; u++) {
        int idx = u * 256 + tid;
        int k = idx >> 5, nq = idx & 31;
        uint32_t dst = sb + (uint32_t)(k * 512 + ((nq ^ (k & 31)) << 4));
        CP_ASYNC16(dst, (const char*)(W + (size_t)(k0 + k) * N + n0 + nq * 4));
    }
    CP_COMMIT();
    CP_WAIT(0);
    __syncthreads();

    const float* t = (const float*)smem;
    int lane = tid & 31, w = tid >> 5;
    int nb = w * 16 + (lane & 3);       // n base for this thread
    int cb = (lane >> 2) & 7;           // k-octet base
    #pragma unroll
    for (int jk = 0; jk < 2; jk++) {
        int c = cb + jk * 8;            // k-octet 0..15
        #pragma unroll
        for (int jn = 0; jn < 4; jn++) {
            int n = nb + jn * 4;
            int nq = n >> 2, n3 = n & 3;
            uint4 v;
            uint32_t* vp = (uint32_t*)&v;
            #pragma unroll
            for (int i = 0; i < 4; i++) {
                int ka = c * 8 + 2 * i, kb2 = ka + 1;
                float a  = t[ka  * 128 + ((nq ^ (ka  & 31)) << 2) + n3];
                float b2 = t[kb2 * 128 + ((nq ^ (kb2 & 31)) << 2) + n3];
                vp[i] = f16 ? pack2h(a, b2) : pack2(a, b2);
            }
            size_t o = (size_t)(n0 + n) * K + k0 + c * 8;
            if (f16) *(uint4*)((__half*)out + o) = v;
            else     *(uint4*)((__nv_bfloat16*)out + o) = v;
        }
    }
}

// ========== GEMM, 256x128 CTA tile, single pass (dtype via idesc), 2 CTAs/SM ==========
// MODE 1: Ch(fp16) = gelu(AB+bias) ; MODE 2: C(fp32) = resid + gate*(AB+bias)
// MODE 3: qkv: cols<2048 -> Ch (bf16, width 2048); cols>=2048 -> Vth (bf16) transposed
#define OFF_TILES 1024
#define GBUFSZ    49152

template<int MODE>
__global__ void __launch_bounds__(256, 2)
tc_gemm_kernel(const __nv_bfloat16* __restrict__ A, const __nv_bfloat16* __restrict__ B,
               uint32_t idesc, const float* __restrict__ bias, float* __restrict__ C,
               void* __restrict__ Ch, __nv_bfloat16* __restrict__ Vth,
               int M, int N, int K,
               const float* __restrict__ resid, const float* __restrict__ gate)
{
#if HAS_TC
    extern __shared__ __align__(1024) char smem[];
    uint32_t smem_base = smem_u32(smem);
    int tid = threadIdx.x;
    int wid = tid >> 5;
    int brow = blockIdx.y * 256;
    int bcol = blockIdx.x * 128;

    if (wid == 0) TC_ALLOC(smem_base, 256);
    if (tid == 0) { MBAR_INIT(smem_base + 16, 1); MBAR_INIT(smem_base + 24, 1); }
    __syncthreads();
    uint32_t tmem;
    asm volatile("ld.shared.b32 %0, [%1];" : "=r"(tmem) : "r"(smem_base));
    if (wid == 0) TC_RELINQ();

    const int NC = K >> 6;

    auto load_chunk = [&](int c, int b) {
        uint32_t bufb = smem_base + OFF_TILES + (uint32_t)b * GBUFSZ;
        int k0 = c << 6;
        #pragma unroll
        for (int i = 0; i < 3; i++) {
            #pragma unroll
            for (int u = 0; u < 4; u++) {
                int idx = u * 256 + tid;
                int r = idx >> 3;
                int o = (idx & 7) * 16;
                uint32_t so = (uint32_t)(i * 16384) + swz((uint32_t)(r * 128 + o));
                const __nv_bfloat16* src;
                if (i == 0)      src = A + (size_t)(brow + r) * K + k0;
                else if (i == 1) src = A + (size_t)(brow + 128 + r) * K + k0;
                else             src = B + (size_t)(bcol + r) * K + k0;
                CP_ASYNC16(bufb + so, (const char*)src + o);
            }
        }
        CP_COMMIT();
    };

    load_chunk(0, 0);

    uint32_t ph0 = 0, ph1 = 0;
    for (int c = 0; c < NC; c++) {
        int b = c & 1;
        if (c + 1 < NC) {
            int nb = (c + 1) & 1;
            if (c >= 1) {
                if (nb == 0) { mbar_wait(smem_base + 16, ph0); ph0 ^= 1; }
                else         { mbar_wait(smem_base + 24, ph1); ph1 ^= 1; }
            }
            load_chunk(c + 1, nb);
            CP_WAIT(1);
        } else {
            CP_WAIT(0);
        }
        FENCE_ASYNC();
        __syncthreads();
        if (wid == 0) {
            if (elect_one()) {
                uint32_t tb = smem_base + OFF_TILES + (uint32_t)b * GBUFSZ;
                uint64_t dB = make_sw128_desc(tb + 32768);
                #pragma unroll
                for (int rb = 0; rb < 2; rb++) {
                    uint32_t d = tmem + (uint32_t)rb * 128;
                    uint64_t dA = make_sw128_desc(tb + rb * 16384);
                    #pragma unroll
                    for (int ks = 0; ks < 4; ks++)
                        tc_mma_f16_ss(d, dA + ks * 2, dB + ks * 2, idesc,
                                      (c == 0 && ks == 0) ? 0u : 1u);
                }
                TC_COMMIT(smem_base + 16 + 8 * b);
            }
        }
    }
    {
        int lb = (NC - 1) & 1;
        if (lb == 0) mbar_wait(smem_base + 16, ph0);
        else         mbar_wait(smem_base + 24, ph1);
    }
    TC_FENCE_AFTER();

    // ---- epilogue: warps 0-3 -> rowblock 0, warps 4-7 -> rowblock 1
    {
        int lane = tid & 31;
        int sp = (tid >> 5) & 3;
        int half = tid >> 7;
        int row = brow + half * 128 + sp * 32 + lane;
        float gv = (MODE == 2) ? gate[0] : 0.f;
        #pragma unroll
        for (int cb = 0; cb < 4; cb++) {
            uint32_t regs[32];
            LDTM_X32(regs, tmem + half * 128 + cb * 32);
            TC_WAIT_LD();
            int cbase = bcol + cb * 32;
            #pragma unroll
            for (int j = 0; j < 8; j++) {
                float4 bb = *(const float4*)(bias + cbase + j * 4);
                float v0 = __uint_as_float(regs[j * 4 + 0]) + bb.x;
                float v1 = __uint_as_float(regs[j * 4 + 1]) + bb.y;
                float v2 = __uint_as_float(regs[j * 4 + 2]) + bb.z;
                float v3 = __uint_as_float(regs[j * 4 + 3]) + bb.w;
                if (MODE == 1) {
                    size_t ro = (size_t)row * N + cbase + j * 4;
                    v0 = 0.5f * v0 * (1.0f + erff(v0 * 0.7071067811865475f));
                    v1 = 0.5f * v1 * (1.0f + erff(v1 * 0.7071067811865475f));
                    v2 = 0.5f * v2 * (1.0f + erff(v2 * 0.7071067811865475f));
                    v3 = 0.5f * v3 * (1.0f + erff(v3 * 0.7071067811865475f));
                    uint2 hh;
                    hh.x = pack2h(v0, v1);
                    hh.y = pack2h(v2, v3);
                    *(uint2*)((__half*)Ch + ro) = hh;
                } else if (MODE == 2) {
                    size_t ro = (size_t)row * N + cbase + j * 4;
                    float4 rr = *(const float4*)(resid + ro);
                    *(float4*)(C + ro) =
                        make_float4(rr.x + gv * v0, rr.y + gv * v1,
                                    rr.z + gv * v2, rr.w + gv * v3);
                } else { // MODE 3 (qkv, bf16)
                    float vv[4] = {v0, v1, v2, v3};
                    if (cbase < 2048) {
                        size_t ro = (size_t)row * 2048 + cbase + j * 4;
                        uint2 hh;
                        hh.x = pack2(v0, v1);
                        hh.y = pack2(v2, v3);
                        *(uint2*)((__nv_bfloat16*)Ch + ro) = hh;
                    } else {
                        int bidx = row >> 10, seq = row & 1023;
                        #pragma unroll
                        for (int e = 0; e < 4; e++) {
                            int col2 = cbase + j * 4 + e - 2048;
                            int hloc = col2 >> 6, d = col2 & 63;
                            size_t vo = ((size_t)((bidx * HEADS + hloc) * HD + d)) * SEQ + seq;
                            Vth[vo] = __float2bfloat16(vv[e]);
                        }
                    }
                }
            }
        }
        TC_FENCE_BEFORE();
    }
    __syncthreads();
    if (wid == 0) TC_DEALLOC(tmem, 256);

#else  // ---------------- SIMT fallback (compiles only; never runs on sm_103a) ----------------
    int tid = threadIdx.x;
    int brow = blockIdx.y * 256;
    int bcol = blockIdx.x * 128;
    int ty = tid >> 4, tx = tid & 15;
    float gv = (MODE == 2 && gate) ? gate[0] : 0.f;
    for (int i = 0; i < 16; i++) {
        for (int j = 0; j < 8; j++) {
            int r = brow + ty * 16 + i;
            int c = bcol + tx * 8 + j;
            float acc = 0.f;
            for (int k = 0; k < K; k++)
                acc = fmaf(bf2f(A[(size_t)r * K + k]), bf2f(B[(size_t)c * K + k]), acc);
            acc += bias[c];
            if (MODE == 1) {
                acc = 0.5f * acc * (1.0f + erff(acc * 0.7071067811865475f));
                ((__half*)Ch)[(size_t)r * N + c] = __float2half(acc);
            } else if (MODE == 2) {
                size_t off = (size_t)r * N + c;
                C[off] = resid[off] + gv * acc;
            } else {
                if (c < 2048) {
                    ((__nv_bfloat16*)Ch)[(size_t)r * 2048 + c] = __float2bfloat16(acc);
                } else {
                    int col2 = c - 2048;
                    int bidx = r >> 10, seq = r & 1023;
                    size_t vo = ((size_t)((bidx * HEADS + (col2 >> 6)) * HD + (col2 & 63))) * SEQ + seq;
                    Vth[vo] = __float2bfloat16(acc);
                }
            }
        }
    }
#endif
}

// ---------------- LayerNorm: fp32 in -> bf16 (OUT=0) or fp16 (OUT=1) ----------------
template<int OUT>
__global__ void __launch_bounds__(256) ln_kernel(
    const float* __restrict__ x, const float* __restrict__ g,
    const float* __restrict__ b, void* __restrict__ y)
{
    int row = blockIdx.x;
    int tid = threadIdx.x;
    const float* xr = x + (size_t)row * DIMN;
    float4 v = *(const float4*)(xr + tid * 4);
    float s  = v.x + v.y + v.z + v.w;
    float s2 = v.x*v.x + v.y*v.y + v.z*v.z + v.w*v.w;
    #pragma unroll
    for (int o = 16; o > 0; o >>= 1) {
        s  += __shfl_xor_sync(0xffffffffu, s,  o);
        s2 += __shfl_xor_sync(0xffffffffu, s2, o);
    }
    __shared__ float rs[8], rs2[8];
    int w = tid >> 5, lane = tid & 31;
    if (lane == 0) { rs[w] = s; rs2[w] = s2; }
    __syncthreads();
    if (tid == 0) {
        float a = 0.f, a2 = 0.f;
        #pragma unroll
        for (int i = 0; i < 8; i++) { a += rs[i]; a2 += rs2[i]; }
        rs[0] = a; rs2[0] = a2;
    }
    __syncthreads();
    float mu   = rs[0] * (1.0f / DIMN);
    float var  = rs2[0] * (1.0f / DIMN) - mu * mu;
    float rstd = rsqrtf(var + 1e-5f);
    float4 gv = *(const float4*)(g + tid * 4);
    float4 bv = *(const float4*)(b + tid * 4);
    float o0 = (v.x - mu) * rstd * gv.x + bv.x;
    float o1 = (v.y - mu) * rstd * gv.y + bv.y;
    float o2 = (v.z - mu) * rstd * gv.z + bv.z;
    float o3 = (v.w - mu) * rstd * gv.w + bv.w;
    uint2 hh;
    if (OUT) { hh.x = pack2h(o0, o1); hh.y = pack2h(o2, o3); }
    else     { hh.x = pack2(o0, o1);  hh.y = pack2(o2, o3);  }
    *(uint2*)((char*)y + ((size_t)row * DIMN + tid * 4) * 2) = hh;
}

// ======== tcgen05 flash attention (bf16, fixed-max, TMEM O, 256-col TMEM, 2 CTAs/SM) ========
#define ASM_FULL0  8
#define ASM_FULL1  16
#define ASM_EK0    24
#define ASM_EK1    32
#define ASM_EV0    40
#define ASM_EV1    48
#define ASM_SDONE  56
#define ASM_PDONE  64
#define ASM_BIAS   128     // 2 x 256 floats
#define ASM_MK     2176    // 2 x 128 floats
#define ASM_MQ     3200    // 128 floats
#define ASM_QHI    4096    // 16KB
#define ASM_BUF    20480   // 2 x 32768
#define ASM_TOTAL  (20480 + 2*32768)
#define IDESC_S  ((1u<<4) | (1u<<7) | (1u<<10) | (16u<<17) | (8u<<24))
#define IDESC_PV ((1u<<4) | (1u<<7) | (1u<<10) | (8u<<17)  | (8u<<24))

__global__ void __launch_bounds__(256, 2)
attn_tc_kernel(const __nv_bfloat16* __restrict__ Qkh,
               const __nv_bfloat16* __restrict__ Vth,
               const int* __restrict__ mask, const float* __restrict__ relb,
               __nv_bfloat16* __restrict__ oh)
{
    int qt = blockIdx.x, h = blockIdx.y, bb = blockIdx.z;
    int tid = threadIdx.x;
#if HAS_TC
    extern __shared__ __align__(1024) char smem[];
    uint32_t base = smem_u32(smem);
    int wid = tid >> 5, lane = tid & 31;
    const size_t qrow0 = (size_t)(bb * SEQ + qt * 128);

    if (wid == 0) TC_ALLOC(base, 256);
    if (tid == 0) {
        MBAR_INIT(base + ASM_FULL0, 128);
        MBAR_INIT(base + ASM_FULL1, 128);
        MBAR_INIT(base + ASM_EK0, 1);
        MBAR_INIT(base + ASM_EK1, 1);
        MBAR_INIT(base + ASM_EV0, 1);
        MBAR_INIT(base + ASM_EV1, 1);
        MBAR_INIT(base + ASM_SDONE, 1);
        MBAR_INIT(base + ASM_PDONE, 1);
    }
    __syncthreads();
    uint32_t tmem;
    asm volatile("ld.shared.b32 %0, [%1];" : "=r"(tmem) : "r"(base));
    if (wid == 0) TC_RELINQ();

    float* bias_s = (float*)(smem + ASM_BIAS);
    float* mk_s   = (float*)(smem + ASM_MK);
    float* mq_s   = (float*)(smem + ASM_MQ);

    if (wid >= 4) {
        // ---------------- producers ----------------
        int pt = tid - 128;
        for (int t = 0; t < 8; t++) {
            int bsel = t & 1;
            int k0 = t * 128;
            char* buf = smem + ASM_BUF + bsel * 32768;
            if (t >= 2) mbar_wait(base + ASM_EK0 + 8 * bsel, ((t >> 1) - 1) & 1);
            #pragma unroll
            for (int i = 0; i < 8; i++) {
                int idx = i * 128 + pt;
                int r = idx >> 3, ch = idx & 7;
                size_t go = (size_t)(bb * SEQ + k0 + r) * 2048 + 1024 + h * HD + ch * 8;
                uint32_t so = swz(r * 128 + ch * 16);
                *(uint4*)(buf + so) = *(const uint4*)(Qkh + go);
            }
            if (t >= 2) mbar_wait(base + ASM_EV0 + 8 * bsel, ((t >> 1) - 1) & 1);
            #pragma unroll
            for (int i = 0; i < 8; i++) {
                int idx = i * 128 + pt;
                int d = idx >> 4, hh2 = (idx >> 3) & 1, ch = idx & 7;
                size_t go = ((size_t)((bb * HEADS + h) * HD + d)) * SEQ + k0 + hh2 * 64 + ch * 8;
                uint32_t so = (uint32_t)(hh2 * 8192) + swz(d * 128 + ch * 16);
                *(uint4*)(buf + 16384 + so) = *(const uint4*)(Vth + go);
            }
            bias_s[bsel * 256 + pt] = relb[(qt * 128 - k0 + pt + 896) * HEADS + h];
            if (pt + 128 < 255)
                bias_s[bsel * 256 + pt + 128] = relb[(qt * 128 - k0 + pt + 128 + 896) * HEADS + h];
            mk_s[bsel * 128 + pt] = (float)mask[bb * SEQ + k0 + pt];
            FENCE_ASYNC();
            MBAR_ARRIVE(base + ASM_FULL0 + 8 * bsel);
        }
    } else {
        // ---------------- consumers ----------------
        int t4 = tid;
        #pragma unroll
        for (int i = 0; i < 8; i++) {
            int idx = i * 128 + t4;
            int r = idx >> 3, ch = idx & 7;
            size_t go = (qrow0 + r) * 2048 + h * HD + ch * 8;
            uint32_t so = swz(r * 128 + ch * 16);
            *(uint4*)(smem + ASM_QHI + so) = *(const uint4*)(Qkh + go);
        }
        mq_s[t4] = (float)mask[qrow0 + t4];
        FENCE_ASYNC();
        asm volatile("bar.sync 7, 128;" ::: "memory");

        int r = wid * 32 + lane;
        float mqr = mq_s[r];
        float lrow = 0.f;
        uint32_t warpoff = (uint32_t)wid << 21;
        uint64_t dQh = make_sw128_desc(base + ASM_QHI);

        if (wid == 0 && elect_one()) {
            mbar_wait(base + ASM_FULL0, 0);
            uint64_t dKh = make_sw128_desc(base + ASM_BUF);
            #pragma unroll
            for (int ks = 0; ks < 4; ks++)
                tc_mma_f16_ss(tmem, dQh + ks * 2, dKh + ks * 2, IDESC_S, ks > 0 ? 1u : 0u);
            TC_COMMIT(base + ASM_SDONE);
        }

        for (int t = 0; t < 8; t++) {
            int bsel = t & 1;
            uint32_t bufb = base + ASM_BUF + bsel * 32768;
            const float* bsf = bias_s + bsel * 256;
            const float* mkf = mk_s + bsel * 128;
            mbar_wait(base + ASM_FULL0 + 8 * bsel, (t >> 1) & 1);
            mbar_wait(base + ASM_SDONE, t & 1);
            TC_FENCE_AFTER();
            if (wid == 0 && elect_one()) MBAR_ARRIVE(base + ASM_EK0 + 8 * bsel);
            if (t >= 1) {
                mbar_wait(base + ASM_PDONE, (t - 1) & 1);
                TC_FENCE_AFTER();
                if (wid == 0 && elect_one()) MBAR_ARRIVE(base + ASM_EV0 + 8 * ((t - 1) & 1));
            }

            float rsum = 0.f;
            #pragma unroll
            for (int j = 0; j < 4; j++) {
                uint32_t sr[32];
                LDTM_X32(sr, tmem + j * 32);
                TC_WAIT_LD();
                uint32_t ph[16];
                #pragma unroll
                for (int k = 0; k < 16; k++) {
                    int c = j * 32 + 2 * k;
                    float va = __uint_as_float(sr[2 * k])     * 0.125f + bsf[r - c + 127];
                    float vb = __uint_as_float(sr[2 * k + 1]) * 0.125f + bsf[r - (c + 1) + 127];
                    va = (mqr * mkf[c]     >= 0.5f) ? va : -1e9f;
                    vb = (mqr * mkf[c + 1] >= 0.5f) ? vb : -1e9f;
                    float ea = __expf(va);
                    float eb = __expf(vb);
                    rsum += ea + eb;
                    ph[k] = pack2(ea, eb);
                }
                STTM_X16(tmem + 192 + j * 16 + warpoff, ph);
            }
            TC_WAIT_ST();
            lrow += rsum;
            TC_FENCE_BEFORE();
            asm volatile("bar.sync 7, 128;" ::: "memory");

            if (wid == 0 && elect_one()) {
                if (t < 7) {
                    int nb = (t + 1) & 1;
                    mbar_wait(base + ASM_FULL0 + 8 * nb, ((t + 1) >> 1) & 1);
                    uint64_t dKh = make_sw128_desc(base + ASM_BUF + nb * 32768);
                    #pragma unroll
                    for (int ks = 0; ks < 4; ks++)
                        tc_mma_f16_ss(tmem, dQh + ks * 2, dKh + ks * 2, IDESC_S, ks > 0 ? 1u : 0u);
                    TC_COMMIT(base + ASM_SDONE);
                }
                uint64_t dVh0 = make_sw128_desc(bufb + 16384);
                uint64_t dVh1 = make_sw128_desc(bufb + 16384 + 8192);
                #pragma unroll
                for (int ks = 0; ks < 8; ks++) {
                    uint64_t dvh = (ks < 4 ? dVh0 : dVh1) + (ks & 3) * 2;
                    tc_mma_f16_ts(tmem + 128, tmem + 192 + ks * 8, dvh, IDESC_PV,
                                  (t == 0 && ks == 0) ? 0u : 1u);
                }
                TC_COMMIT(base + ASM_PDONE);
            }
        }

        mbar_wait(base + ASM_PDONE, 1);
        TC_FENCE_AFTER();
        uint32_t pv0[32], pv1[32];
        LDTM_X32(pv0, tmem + 128);
        TC_WAIT_LD();
        LDTM_X32(pv1, tmem + 160);
        TC_WAIT_LD();
        TC_FENCE_BEFORE();
        float inv = 1.0f / lrow;
        size_t orow = (qrow0 + r) * DIMN + h * HD;
        uint32_t* po = (uint32_t*)(oh + orow);
        #pragma unroll
        for (int j = 0; j < 16; j++)
            po[j] = pack2(__uint_as_float(pv0[2 * j]) * inv, __uint_as_float(pv0[2 * j + 1]) * inv);
        #pragma unroll
        for (int j = 0; j < 16; j++)
            po[16 + j] = pack2(__uint_as_float(pv1[2 * j]) * inv, __uint_as_float(pv1[2 * j + 1]) * inv);
    }
    __syncthreads();
    if (wid == 0) TC_DEALLOC(tmem, 256);
#else
    // naive fallback (compiles only)
    int r = tid;
    if (r < 128) {
        int q = qt * 128 + r;
        size_t qro = (size_t)(bb * SEQ + q) * 2048 + h * HD;
        float mqr = (float)mask[bb * SEQ + q];
        float lrow = 0.f, O[64];
        for (int d = 0; d < 64; d++) O[d] = 0.f;
        for (int k = 0; k < SEQ; k++) {
            float s = 0.f;
            size_t kro = (size_t)(bb * SEQ + k) * 2048 + 1024 + h * HD;
            for (int d = 0; d < 64; d++)
                s = fmaf(bf2f(Qkh[qro + d]), bf2f(Qkh[kro + d]), s);
            s = s * 0.125f + relb[(q - k + SEQ - 1) * HEADS + h];
            float mk2 = (float)mask[bb * SEQ + k];
            s = (mqr * mk2 >= 0.5f) ? s : -1e9f;
            float p = expf(s);
            lrow += p;
            size_t vro = ((size_t)((bb * HEADS + h) * HD)) * SEQ + k;
            for (int d = 0; d < 64; d++)
                O[d] += p * bf2f(Vth[vro + (size_t)d * SEQ]);
        }
        size_t orow = (size_t)(bb * SEQ + q) * DIMN + h * HD;
        for (int d = 0; d < 64; d++)
            oh[orow + d] = __float2bfloat16(O[d] / lrow);
    }
#endif
}

// ---------------- host launcher ----------------
extern "C" void kernel_launch(void* const* d_in, const int* in_sizes, int n_in,
                              void* d_out, int out_size)
{
    const float* x      = (const float*)d_in[0];
    const int*   mask   = (const int*)  d_in[1];
    const float* ln1_g  = (const float*)d_in[2];
    const float* ln1_b  = (const float*)d_in[3];
    const float* qkv_w  = (const float*)d_in[4];
    const float* qkv_b  = (const float*)d_in[5];
    const float* proj_w = (const float*)d_in[6];
    const float* proj_b = (const float*)d_in[7];
    const float* relb   = (const float*)d_in[8];
    const float* ln2_g  = (const float*)d_in[9];
    const float* ln2_b  = (const float*)d_in[10];
    const float* mlp_w1 = (const float*)d_in[11];
    const float* mlp_b1 = (const float*)d_in[12];
    const float* mlp_w2 = (const float*)d_in[13];
    const float* mlp_b2 = (const float*)d_in[14];
    const float* gate1  = (const float*)d_in[15];
    const float* gate2  = (const float*)d_in[16];
    float* out = (float*)d_out;

    float *x1b;
    __nv_bfloat16 *ab, *wtb, *qkh, *vth;
    __half *hb, *w1h, *w2h;
    cudaGetSymbolAddress((void**)&x1b, g_x1);
    cudaGetSymbolAddress((void**)&ab,  g_a);
    cudaGetSymbolAddress((void**)&hb,  g_h);
    cudaGetSymbolAddress((void**)&wtb, g_wt_bf);
    cudaGetSymbolAddress((void**)&qkh, g_qk);
    cudaGetSymbolAddress((void**)&vth, g_vt);
    cudaGetSymbolAddress((void**)&w1h, g_w1_16);
    cudaGetSymbolAddress((void**)&w2h, g_w2_16);

    int smem_gemm = OFF_TILES + 2 * GBUFSZ;   // 99328
    cudaFuncSetAttribute(tc_gemm_kernel<1>, cudaFuncAttributeMaxDynamicSharedMemorySize, smem_gemm);
    cudaFuncSetAttribute(tc_gemm_kernel<2>, cudaFuncAttributeMaxDynamicSharedMemorySize, smem_gemm);
    cudaFuncSetAttribute(tc_gemm_kernel<3>, cudaFuncAttributeMaxDynamicSharedMemorySize, smem_gemm);
    cudaFuncSetAttribute(attn_tc_kernel, cudaFuncAttributeMaxDynamicSharedMemorySize, ASM_TOTAL);
    cudaFuncSetAttribute(wconv_kernel, cudaFuncAttributeMaxDynamicSharedMemorySize, 65536);

    // 0) fused weight transpose+convert pre-pass (one launch, 768 tiles)
    wconv_kernel<<<768, 256, 65536>>>(qkv_w, proj_w, mlp_w1, mlp_w2,
                                      wtb + WOFF_QKV, wtb + WOFF_PROJ, w1h, w2h);

    // 1) LN1 -> a (bf16)
    ln_kernel<0><<<ROWS, 256>>>(x, ln1_g, ln1_b, ab);
    // 2) QKV GEMM (bf16) -> qk + vt
    tc_gemm_kernel<3><<<dim3(3 * DIMN / 128, ROWS / 256), 256, smem_gemm>>>(
        ab, wtb + WOFF_QKV, IDESC_BF16, qkv_b, nullptr, qkh, vth,
        ROWS, 3 * DIMN, DIMN, nullptr, nullptr);
    // 3) tcgen05 attention (bf16) -> a
    attn_tc_kernel<<<dim3(SEQ / 128, HEADS, BATCH), 256, ASM_TOTAL>>>(
        qkh, vth, mask, relb, ab);
    // 4) x1 = x + gate1 * (a @ proj_w + proj_b)  (bf16)
    tc_gemm_kernel<2><<<dim3(DIMN / 128, ROWS / 256), 256, smem_gemm>>>(
        ab, wtb + WOFF_PROJ, IDESC_BF16, proj_b, x1b, nullptr, nullptr,
        ROWS, DIMN, DIMN, x, gate1);
    // 5) LN2 -> a (fp16, reinterpret buffer)
    ln_kernel<1><<<ROWS, 256>>>(x1b, ln2_g, ln2_b, ab);
    // 6) h = gelu(a @ mlp_w1 + mlp_b1)  (fp16 single pass)
    tc_gemm_kernel<1><<<dim3(4 * DIMN / 128, ROWS / 256), 256, smem_gemm>>>(
        (const __nv_bfloat16*)ab, (const __nv_bfloat16*)w1h, IDESC_FP16, mlp_b1,
        nullptr, hb, nullptr, ROWS, 4 * DIMN, DIMN, nullptr, nullptr);
    // 7) out = x1 + gate2 * (h @ mlp_w2 + mlp_b2)  (fp16 single pass)
    tc_gemm_kernel<2><<<dim3(DIMN / 128, ROWS / 256), 256, smem_gemm>>>(
        (const __nv_bfloat16*)hb, (const __nv_bfloat16*)w2h, IDESC_FP16, mlp_b2,
        out, nullptr, nullptr, ROWS, DIMN, 4 * DIMN, x1b, gate2);
}